// round 14
// baseline (speedup 1.0000x reference)
#include <cuda_runtime.h>
#include <cuda_bf16.h>
#include <cuda_fp16.h>
#include <math.h>
#include <cstdint>

// ---------------------------------------------------------------------------
// GCN: 3x { H = A_sparse @ (H @ W) + b (,ReLU) } -> log_softmax
// N=50000, E=1.6M, 512 -> 128 -> 128 -> 40
// Round 14: R13 (best: 275.2) + split-half pipelining: row-local GEMMs
//           (gemm2, sgemm40) overlap the second half of the preceding spmm.
// ---------------------------------------------------------------------------

#define NNODES 50000
#define NEDGES 1600000
#define NFEAT 512
#define NHID  128
#define NCLASS 40
#define MSPLIT 24960   // half-point: multiple of 128 (gemm tile) and 8 (spmm)

// Scratch (__device__ globals; no allocations allowed)
__device__ __half g_Ah[NNODES * NHID];
__device__ __half g_Bh[NNODES * NHID];
__device__ __half g_Ch[NNODES * NCLASS];
__device__ int    g_cnt[NNODES];
__device__ int    g_cursor[NNODES];
__device__ int    g_rp[NNODES + 1];
__device__ int    g_tmp[NNODES];
__device__ int    g_bsum[256];
__device__ uint32_t g_pe[NEDGES];        // packed (fp16 w << 16 | u16 src)
__device__ uint32_t g_W1h[256 * 128];
__device__ uint32_t g_W1l[256 * 128];
__device__ uint32_t g_Whh[64 * 128];
__device__ uint32_t g_Whl[64 * 128];

// ===========================================================================
// helpers
// ===========================================================================
__device__ __forceinline__ void cvt_hilo(float x, float y, uint32_t& hi, uint32_t& lo) {
    __nv_bfloat16 hx = __float2bfloat16(x);
    __nv_bfloat16 hy = __float2bfloat16(y);
    float rx = x - __bfloat162float(hx);
    float ry = y - __bfloat162float(hy);
    __nv_bfloat162 H; H.x = hx; H.y = hy;
    __nv_bfloat162 L; L.x = __float2bfloat16(rx); L.y = __float2bfloat16(ry);
    hi = *reinterpret_cast<uint32_t*>(&H);
    lo = *reinterpret_cast<uint32_t*>(&L);
}

__device__ __forceinline__ void mma16816(float* d, const uint32_t* a, uint32_t b0, uint32_t b1) {
    asm volatile(
        "mma.sync.aligned.m16n8k16.row.col.f32.bf16.bf16.f32 "
        "{%0,%1,%2,%3}, {%4,%5,%6,%7}, {%8,%9}, {%0,%1,%2,%3};"
        : "+f"(d[0]), "+f"(d[1]), "+f"(d[2]), "+f"(d[3])
        : "r"(a[0]), "r"(a[1]), "r"(a[2]), "r"(a[3]), "r"(b0), "r"(b1));
}

__device__ __forceinline__ float4 load4f(const float* p) {
    return *reinterpret_cast<const float4*>(p);
}
__device__ __forceinline__ float4 load4f(const __half* p) {
    uint2 u = *reinterpret_cast<const uint2*>(p);
    float2 a = __half22float2(*reinterpret_cast<__half2*>(&u.x));
    float2 b = __half22float2(*reinterpret_cast<__half2*>(&u.y));
    return make_float4(a.x, a.y, b.x, b.y);
}

__device__ __forceinline__ void unpack_edge(uint32_t rec, int& s, float& w) {
    s = (int)(rec & 0xFFFFu);
    w = __half2float(__ushort_as_half((unsigned short)(rec >> 16)));
}

// SMEM layout (u32 units). A tiles: [m=128][k2=32 + pad4]. B: [k2=32][n=128+8].
#define AH_OFF 0
#define AL_OFF 4608
#define BH_OFF 9216
#define BL_OFF 13568
#define SM_U32 17920   // 71680 bytes

// ===========================================================================
// Weight pre-pack
// ===========================================================================
__global__ void conv_weights(const float* __restrict__ W1, const float* __restrict__ Wh,
                             uint32_t* __restrict__ W1h, uint32_t* __restrict__ W1l,
                             uint32_t* __restrict__ Whh, uint32_t* __restrict__ Whl) {
    int i = blockIdx.x * 256 + threadIdx.x;
    if (i < 256 * 128) {
        int k2 = i >> 7, n = i & 127;
        float v0 = __ldg(W1 + (size_t)(2 * k2) * 128 + n);
        float v1 = __ldg(W1 + (size_t)(2 * k2 + 1) * 128 + n);
        uint32_t h, lo;
        cvt_hilo(v0, v1, h, lo);
        W1h[i] = h; W1l[i] = lo;
    } else if (i < 256 * 128 + 64 * 128) {
        int j = i - 256 * 128;
        int k2 = j >> 7, n = j & 127;
        float v0 = __ldg(Wh + (size_t)(2 * k2) * 128 + n);
        float v1 = __ldg(Wh + (size_t)(2 * k2 + 1) * 128 + n);
        uint32_t h, lo;
        cvt_hilo(v0, v1, h, lo);
        Whh[j] = h; Whl[j] = lo;
    }
}

// ===========================================================================
// mma.sync GEMM over rows [rowBase, rowEnd): C = A @ Wpacked, fp16 out.
// ===========================================================================
template <typename TIn>
__global__ void __launch_bounds__(256, 2) mma_gemm128(
    const TIn* __restrict__ A,
    const uint32_t* __restrict__ Wph, const uint32_t* __restrict__ Wpl,
    __half* __restrict__ C, int rowBase, int rowEnd, int K) {
    extern __shared__ uint32_t sm[];
    uint32_t* AH = sm + AH_OFF;
    uint32_t* AL = sm + AL_OFF;
    uint32_t* BH = sm + BH_OFF;
    uint32_t* BL = sm + BL_OFF;

    const int t = threadIdx.x;
    const int lane = t & 31;
    const int wid = t >> 5;
    const int warpM = wid >> 1;
    const int warpN = wid & 1;
    const int row0 = rowBase + blockIdx.x * 128;

    float acc[2][8][4];
#pragma unroll
    for (int mt = 0; mt < 2; mt++)
#pragma unroll
        for (int nt = 0; nt < 8; nt++)
#pragma unroll
            for (int e = 0; e < 4; e++) acc[mt][nt][e] = 0.f;

    const int r4 = lane >> 2;
    const int q4 = lane & 3;

    const int nChunks = K >> 6;
    for (int c = 0; c < nChunks; c++) {
        const int k0 = c << 6;
        const int k0h = c << 5;
        __syncthreads();

#pragma unroll
        for (int l = 0; l < 8; l++) {
            int q = t + l * 256;
            int m = q >> 4;
            int c4 = q & 15;
            float4 v = make_float4(0.f, 0.f, 0.f, 0.f);
            if (row0 + m < rowEnd)
                v = load4f(A + (size_t)(row0 + m) * K + k0 + c4 * 4);
            uint32_t h0, l0, h1, l1;
            cvt_hilo(v.x, v.y, h0, l0);
            cvt_hilo(v.z, v.w, h1, l1);
            int base = m * 36 + c4 * 2;
            AH[base] = h0; AH[base + 1] = h1;
            AL[base] = l0; AL[base + 1] = l1;
        }
#pragma unroll
        for (int l = 0; l < 4; l++) {
            int q = t + l * 256;
            int k2 = q >> 5;
            int n4 = q & 31;
            size_t goff = (size_t)(k0h + k2) * 128 + n4 * 4;
            uint4 vh = __ldg(reinterpret_cast<const uint4*>(Wph + goff));
            uint4 vl = __ldg(reinterpret_cast<const uint4*>(Wpl + goff));
            *reinterpret_cast<uint4*>(&BH[k2 * 136 + n4 * 4]) = vh;
            *reinterpret_cast<uint4*>(&BL[k2 * 136 + n4 * 4]) = vl;
        }
        __syncthreads();

#pragma unroll
        for (int k8 = 0; k8 < 4; k8++) {
            int klo = k8 * 8 + q4;
            uint32_t ah[2][4], al[2][4];
#pragma unroll
            for (int mt = 0; mt < 2; mt++) {
                int base = (warpM * 32 + mt * 16 + r4) * 36;
                ah[mt][0] = AH[base + klo];
                ah[mt][1] = AH[base + 8 * 36 + klo];
                ah[mt][2] = AH[base + klo + 4];
                ah[mt][3] = AH[base + 8 * 36 + klo + 4];
                al[mt][0] = AL[base + klo];
                al[mt][1] = AL[base + 8 * 36 + klo];
                al[mt][2] = AL[base + klo + 4];
                al[mt][3] = AL[base + 8 * 36 + klo + 4];
            }
#pragma unroll
            for (int nt = 0; nt < 8; nt++) {
                int nB = warpN * 64 + nt * 8 + r4;
                uint32_t bh0 = BH[klo * 136 + nB];
                uint32_t bh1 = BH[(klo + 4) * 136 + nB];
                uint32_t bl0 = BL[klo * 136 + nB];
                uint32_t bl1 = BL[(klo + 4) * 136 + nB];
#pragma unroll
                for (int mt = 0; mt < 2; mt++) {
                    mma16816(acc[mt][nt], ah[mt], bh0, bh1);
                    mma16816(acc[mt][nt], ah[mt], bl0, bl1);
                    mma16816(acc[mt][nt], al[mt], bh0, bh1);
                }
            }
        }
    }

#pragma unroll
    for (int mt = 0; mt < 2; mt++) {
        int rowA = row0 + warpM * 32 + mt * 16 + r4;
        int rowB = rowA + 8;
#pragma unroll
        for (int nt = 0; nt < 8; nt++) {
            int col = warpN * 64 + nt * 8 + q4 * 2;
            if (rowA < rowEnd)
                *reinterpret_cast<__half2*>(C + (size_t)rowA * 128 + col) =
                    __floats2half2_rn(acc[mt][nt][0], acc[mt][nt][1]);
            if (rowB < rowEnd)
                *reinterpret_cast<__half2*>(C + (size_t)rowB * 128 + col) =
                    __floats2half2_rn(acc[mt][nt][2], acc[mt][nt][3]);
        }
    }
}

// ===========================================================================
// CSR build
// ===========================================================================
__global__ void zero_int4(int4* p, int n4) {
    int i = blockIdx.x * blockDim.x + threadIdx.x;
    if (i < n4) p[i] = make_int4(0, 0, 0, 0);
}

__global__ void hist_dst4(const int4* __restrict__ dst4, int* __restrict__ cnt, int n4) {
    int e = blockIdx.x * blockDim.x + threadIdx.x;
    if (e >= n4) return;
    int4 d = __ldg(dst4 + e);
    atomicAdd(&cnt[d.x], 1);
    atomicAdd(&cnt[d.y], 1);
    atomicAdd(&cnt[d.z], 1);
    atomicAdd(&cnt[d.w], 1);
}

__global__ void scan_p1(const int* __restrict__ cnt, int* __restrict__ tmp,
                        int* __restrict__ bsum, int n) {
    __shared__ int wsum[8];
    const int lane = threadIdx.x & 31;
    const int wid  = threadIdx.x >> 5;
    int i = blockIdx.x * 256 + threadIdx.x;
    int v = (i < n) ? cnt[i] : 0;
    int incl = v;
#pragma unroll
    for (int o = 1; o < 32; o <<= 1) {
        int tt = __shfl_up_sync(0xffffffffu, incl, o);
        if (lane >= o) incl += tt;
    }
    if (lane == 31) wsum[wid] = incl;
    __syncthreads();
    if (wid == 0) {
        int s = (lane < 8) ? wsum[lane] : 0;
#pragma unroll
        for (int o = 1; o < 8; o <<= 1) {
            int tt = __shfl_up_sync(0xffffffffu, s, o);
            if (lane >= o) s += tt;
        }
        if (lane < 8) wsum[lane] = s;
    }
    __syncthreads();
    int excl = (wid ? wsum[wid - 1] : 0) + incl - v;
    if (i < n) tmp[i] = excl;
    if (threadIdx.x == 255) bsum[blockIdx.x] = excl + v;
}

__global__ void scan_p3(const int* __restrict__ tmp, const int* __restrict__ bsum,
                        int* __restrict__ rp, int* __restrict__ cursor,
                        int n, int nb, int nE) {
    __shared__ int red[8];
    const int lane = threadIdx.x & 31;
    const int wid  = threadIdx.x >> 5;
    int v = (threadIdx.x < nb && threadIdx.x < blockIdx.x) ? __ldg(bsum + threadIdx.x) : 0;
#pragma unroll
    for (int o = 16; o > 0; o >>= 1) v += __shfl_xor_sync(0xffffffffu, v, o);
    if (lane == 0) red[wid] = v;
    __syncthreads();
    if (threadIdx.x == 0) {
        int s = 0;
#pragma unroll
        for (int j = 0; j < 8; j++) s += red[j];
        red[0] = s;
    }
    __syncthreads();
    int off = red[0];
    int i = blockIdx.x * 256 + threadIdx.x;
    if (i < n) {
        int val = tmp[i] + off;
        rp[i] = val;
        cursor[i] = val;
    }
    if (blockIdx.x == 0 && threadIdx.x == 0) rp[n] = nE;
}

__global__ void scatter_edges4(const int* __restrict__ src, const int* __restrict__ dst,
                               const float* __restrict__ w, int* __restrict__ cursor,
                               uint32_t* __restrict__ pe, int nE) {
    int i = blockIdx.x * blockDim.x + threadIdx.x;
    int e0 = i * 4;
    if (e0 + 4 <= nE) {
        int4 s = __ldg((const int4*)(src + e0));
        int4 d = __ldg((const int4*)(dst + e0));
        float4 ww = __ldg((const float4*)(w + e0));
        uint32_t r0 = (uint32_t)s.x | ((uint32_t)__half_as_ushort(__float2half_rn(ww.x)) << 16);
        uint32_t r1 = (uint32_t)s.y | ((uint32_t)__half_as_ushort(__float2half_rn(ww.y)) << 16);
        uint32_t r2 = (uint32_t)s.z | ((uint32_t)__half_as_ushort(__float2half_rn(ww.z)) << 16);
        uint32_t r3 = (uint32_t)s.w | ((uint32_t)__half_as_ushort(__float2half_rn(ww.w)) << 16);
        int p0 = atomicAdd(&cursor[d.x], 1);
        pe[p0] = r0;
        int p1 = atomicAdd(&cursor[d.y], 1);
        pe[p1] = r1;
        int p2 = atomicAdd(&cursor[d.z], 1);
        pe[p2] = r2;
        int p3 = atomicAdd(&cursor[d.w], 1);
        pe[p3] = r3;
    } else {
        for (int e = e0; e < nE; e++) {
            int dd = __ldg(dst + e);
            int pos = atomicAdd(&cursor[dd], 1);
            pe[pos] = (uint32_t)__ldg(src + e) |
                      ((uint32_t)__half_as_ushort(__float2half_rn(__ldg(w + e))) << 16);
        }
    }
}

// ===========================================================================
// GEMM3 over rows [rowBase, rowEnd): C[.,40] = H[.,128] @ W2
// ===========================================================================
__global__ void sgemm40(const __half* __restrict__ H, const float* __restrict__ W,
                        __half* __restrict__ C, int rowBase, int rowEnd) {
    __shared__ float Ht[32][132];
    __shared__ float Ws[128][40];

    const int t = threadIdx.x;
    const int row0 = rowBase + blockIdx.x * 32;

#pragma unroll
    for (int l = 0; l < 4; l++) {
        int q = t + l * 256;
        int r = q >> 5;
        int c4 = q & 31;
        float4 v = make_float4(0.f, 0.f, 0.f, 0.f);
        if (row0 + r < rowEnd)
            v = load4f(H + (size_t)(row0 + r) * 128 + c4 * 4);
        *reinterpret_cast<float4*>(&Ht[r][c4 * 4]) = v;
    }
#pragma unroll
    for (int l = 0; l < 20; l++) {
        int q = t + l * 256;
        Ws[q / 40][q % 40] = W[q];
    }
    __syncthreads();

    const int r = t >> 3;
    const int cg = t & 7;
    float acc[5] = {0.f, 0.f, 0.f, 0.f, 0.f};
#pragma unroll 8
    for (int k = 0; k < 128; k++) {
        float h = Ht[r][k];
#pragma unroll
        for (int j = 0; j < 5; j++)
            acc[j] = fmaf(h, Ws[k][cg * 5 + j], acc[j]);
    }
    int grow = row0 + r;
    if (grow < rowEnd) {
#pragma unroll
        for (int j = 0; j < 5; j++)
            C[(size_t)grow * 40 + cg * 5 + j] = __float2half_rn(acc[j]);
    }
}

// ===========================================================================
// Gather SpMM (feat=128) over rows [rowBase, rowEnd) + bias + ReLU
// ===========================================================================
__device__ __forceinline__ void acc4h(float& ax, float& ay, float& az, float& aw,
                                      float w, uint2 r) {
    float2 a01 = __half22float2(*reinterpret_cast<__half2*>(&r.x));
    float2 a23 = __half22float2(*reinterpret_cast<__half2*>(&r.y));
    ax = fmaf(w, a01.x, ax); ay = fmaf(w, a01.y, ay);
    az = fmaf(w, a23.x, az); aw = fmaf(w, a23.y, aw);
}

__global__ void __launch_bounds__(256) spmm_csr128h(
    const __half* __restrict__ H, const int* __restrict__ rp,
    const uint32_t* __restrict__ pe, const float* __restrict__ bias,
    __half* __restrict__ out, int rowBase, int rowEnd) {
    int row = rowBase + blockIdx.x * 8 + (threadIdx.x >> 5);
    int lane = threadIdx.x & 31;
    if (row >= rowEnd) return;
    int p  = __ldg(rp + row);
    int pend = __ldg(rp + row + 1);

    const char* Hb = reinterpret_cast<const char*>(H) + lane * 8;
    float ax = 0.f, ay = 0.f, az = 0.f, aw = 0.f;

    for (; p + 4 <= pend; p += 4) {
        uint32_t e0 = __ldg(pe + p + 0), e1 = __ldg(pe + p + 1);
        uint32_t e2 = __ldg(pe + p + 2), e3 = __ldg(pe + p + 3);
        int s0, s1, s2, s3;
        float w0, w1, w2, w3;
        unpack_edge(e0, s0, w0);
        unpack_edge(e1, s1, w1);
        unpack_edge(e2, s2, w2);
        unpack_edge(e3, s3, w3);
        uint2 r0 = *reinterpret_cast<const uint2*>(Hb + (size_t)s0 * 256);
        uint2 r1 = *reinterpret_cast<const uint2*>(Hb + (size_t)s1 * 256);
        uint2 r2 = *reinterpret_cast<const uint2*>(Hb + (size_t)s2 * 256);
        uint2 r3 = *reinterpret_cast<const uint2*>(Hb + (size_t)s3 * 256);
        acc4h(ax, ay, az, aw, w0, r0);
        acc4h(ax, ay, az, aw, w1, r1);
        acc4h(ax, ay, az, aw, w2, r2);
        acc4h(ax, ay, az, aw, w3, r3);
    }
    for (; p < pend; p++) {
        int s;
        float w;
        unpack_edge(__ldg(pe + p), s, w);
        uint2 r0 = *reinterpret_cast<const uint2*>(Hb + (size_t)s * 256);
        acc4h(ax, ay, az, aw, w, r0);
    }

    float4 b4 = *reinterpret_cast<const float4*>(bias + lane * 4);
    __half2 o01 = __floats2half2_rn(fmaxf(ax + b4.x, 0.f), fmaxf(ay + b4.y, 0.f));
    __half2 o23 = __floats2half2_rn(fmaxf(az + b4.z, 0.f), fmaxf(aw + b4.w, 0.f));
    uint2 st;
    st.x = *reinterpret_cast<uint32_t*>(&o01);
    st.y = *reinterpret_cast<uint32_t*>(&o23);
    *reinterpret_cast<uint2*>(reinterpret_cast<char*>(out) + (size_t)row * 256 + lane * 8) = st;
}

// ===========================================================================
// Gather SpMM (feat=40) + bias + log_softmax (full M)
// ===========================================================================
__global__ void __launch_bounds__(256) spmm_csr40_lsm(
    const __half* __restrict__ C, const int* __restrict__ rp,
    const uint32_t* __restrict__ pe, const float* __restrict__ b,
    float* __restrict__ out, int M) {
    int row = blockIdx.x * 8 + (threadIdx.x >> 5);
    int lane = threadIdx.x & 31;
    if (row >= M) return;
    int p  = __ldg(rp + row);
    int pend = __ldg(rp + row + 1);

    float a0 = 0.f, a1 = 0.f;
    for (; p + 2 <= pend; p += 2) {
        int s0, s1;
        float w0, w1;
        unpack_edge(__ldg(pe + p), s0, w0);
        unpack_edge(__ldg(pe + p + 1), s1, w1);
        const __half* c0 = C + (size_t)s0 * 40;
        const __half* c1 = C + (size_t)s1 * 40;
        float x0 = __half2float(__ldg(c0 + lane));
        float x1 = __half2float(__ldg(c1 + lane));
        float y0 = (lane < 8) ? __half2float(__ldg(c0 + 32 + lane)) : 0.f;
        float y1 = (lane < 8) ? __half2float(__ldg(c1 + 32 + lane)) : 0.f;
        a0 = fmaf(w0, x0, a0); a0 = fmaf(w1, x1, a0);
        a1 = fmaf(w0, y0, a1); a1 = fmaf(w1, y1, a1);
    }
    if (p < pend) {
        int s;
        float w;
        unpack_edge(__ldg(pe + p), s, w);
        const __half* c0 = C + (size_t)s * 40;
        a0 = fmaf(w, __half2float(__ldg(c0 + lane)), a0);
        if (lane < 8) a1 = fmaf(w, __half2float(__ldg(c0 + 32 + lane)), a1);
    }

    float v0 = a0 + __ldg(b + lane);
    float v1 = (lane < 8) ? (a1 + __ldg(b + 32 + lane)) : -INFINITY;

    float m = fmaxf(v0, v1);
#pragma unroll
    for (int o = 16; o > 0; o >>= 1) m = fmaxf(m, __shfl_xor_sync(0xffffffffu, m, o));
    float s = __expf(v0 - m) + ((lane < 8) ? __expf(v1 - m) : 0.f);
#pragma unroll
    for (int o = 16; o > 0; o >>= 1) s += __shfl_xor_sync(0xffffffffu, s, o);
    float ls = m + __logf(s);

    out[(size_t)row * 40 + lane] = v0 - ls;
    if (lane < 8) out[(size_t)row * 40 + 32 + lane] = v1 - ls;
}

// ===========================================================================
extern "C" void kernel_launch(void* const* d_in, const int* in_sizes, int n_in,
                              void* d_out, int out_size) {
    const float* x    = (const float*)d_in[0];
    const int*   esrc = (const int*)  d_in[1];
    const int*   edst = (const int*)  d_in[2];
    const float* ew   = (const float*)d_in[3];
    const float* W1   = (const float*)d_in[4];
    const float* b1   = (const float*)d_in[5];
    const float* Wh   = (const float*)d_in[6];
    const float* bh   = (const float*)d_in[7];
    const float* W2   = (const float*)d_in[8];
    const float* b2   = (const float*)d_in[9];
    float* out = (float*)d_out;

    const int M  = in_sizes[0] / NFEAT;   // 50000
    const int nE = in_sizes[1];           // 1600000

    __half *Ah, *Bh, *Ch;
    int *cnt, *cursor, *rp, *tmp, *bsum;
    uint32_t *pe;
    uint32_t *W1h, *W1l, *Whh, *Whl;
    cudaGetSymbolAddress((void**)&Ah, g_Ah);
    cudaGetSymbolAddress((void**)&Bh, g_Bh);
    cudaGetSymbolAddress((void**)&Ch, g_Ch);
    cudaGetSymbolAddress((void**)&cnt, g_cnt);
    cudaGetSymbolAddress((void**)&cursor, g_cursor);
    cudaGetSymbolAddress((void**)&rp, g_rp);
    cudaGetSymbolAddress((void**)&tmp, g_tmp);
    cudaGetSymbolAddress((void**)&bsum, g_bsum);
    cudaGetSymbolAddress((void**)&pe, g_pe);
    cudaGetSymbolAddress((void**)&W1h, g_W1h);
    cudaGetSymbolAddress((void**)&W1l, g_W1l);
    cudaGetSymbolAddress((void**)&Whh, g_Whh);
    cudaGetSymbolAddress((void**)&Whl, g_Whl);

    static cudaStream_t s2 = nullptr;
    static cudaEvent_t evF = nullptr, evJ = nullptr;
    static cudaEvent_t e1 = nullptr, e2 = nullptr, e3 = nullptr, e4 = nullptr;
    if (!s2) {
        cudaStreamCreateWithFlags(&s2, cudaStreamNonBlocking);
        cudaEventCreateWithFlags(&evF, cudaEventDisableTiming);
        cudaEventCreateWithFlags(&evJ, cudaEventDisableTiming);
        cudaEventCreateWithFlags(&e1, cudaEventDisableTiming);
        cudaEventCreateWithFlags(&e2, cudaEventDisableTiming);
        cudaEventCreateWithFlags(&e3, cudaEventDisableTiming);
        cudaEventCreateWithFlags(&e4, cudaEventDisableTiming);
        cudaFuncSetAttribute(mma_gemm128<float>,
                             cudaFuncAttributeMaxDynamicSharedMemorySize, SM_U32 * 4);
        cudaFuncSetAttribute(mma_gemm128<__half>,
                             cudaFuncAttributeMaxDynamicSharedMemorySize, SM_U32 * 4);
    }

    const int nb = (M + 255) / 256;           // 196
    const int nE4 = (nE + 3) / 4;

    const int M1 = MSPLIT;                    // 24960
    const int spmmB1 = M1 / 8;                // 3120
    const int spmmB2 = (M - M1 + 7) / 8;      // 3130
    const int gemmB1 = M1 / 128;              // 195
    const int gemmB2 = (M - M1 + 127) / 128;  // 196
    const int g40B1  = M1 / 32;               // 780
    const int g40B2  = (M - M1 + 31) / 32;    // 783
    const int gemmBlocksAll = (M + 127) / 128;
    const int spmmBlocksAll = (M + 7) / 8;

    // ---- Fork: CSR build on s2, weight pack + layer-1 GEMM on main ----
    cudaEventRecord(evF, 0);
    cudaStreamWaitEvent(s2, evF, 0);

    zero_int4<<<(M / 4 + 255) / 256, 256, 0, s2>>>((int4*)cnt, (M + 3) / 4);
    hist_dst4<<<((nE / 4) + 255) / 256, 256, 0, s2>>>((const int4*)edst, cnt, nE / 4);
    scan_p1<<<nb, 256, 0, s2>>>(cnt, tmp, bsum, M);
    scan_p3<<<nb, 256, 0, s2>>>(tmp, bsum, rp, cursor, M, nb, nE);
    scatter_edges4<<<(nE4 + 255) / 256, 256, 0, s2>>>(esrc, edst, ew, cursor, pe, nE);
    cudaEventRecord(evJ, s2);

    conv_weights<<<160, 256>>>(W1, Wh, W1h, W1l, Whh, Whl);
    mma_gemm128<float><<<gemmBlocksAll, 256, SM_U32 * 4>>>(x, W1h, W1l, Ah, 0, M, NFEAT);

    cudaStreamWaitEvent(0, evJ, 0);   // join: CSR ready

    // ---- Layer 1 aggregation, split halves; gemm2-h1 overlaps spmm1-h2 ----
    spmm_csr128h<<<spmmB1, 256>>>(Ah, rp, pe, b1, Bh, 0, M1);
    cudaEventRecord(e1, 0);
    spmm_csr128h<<<spmmB2, 256>>>(Ah, rp, pe, b1, Bh, M1, M);

    cudaStreamWaitEvent(s2, e1, 0);
    mma_gemm128<__half><<<gemmB1, 256, SM_U32 * 4, s2>>>(Bh, Whh, Whl, Ah, 0, M1, NHID);
    cudaEventRecord(e2, s2);

    mma_gemm128<__half><<<gemmB2, 256, SM_U32 * 4>>>(Bh, Whh, Whl, Ah, M1, M, NHID);
    cudaStreamWaitEvent(0, e2, 0);    // Ah fully ready

    // ---- Layer 2 aggregation, split halves; sgemm40-h1 overlaps spmm2-h2 ----
    spmm_csr128h<<<spmmB1, 256>>>(Ah, rp, pe, bh, Bh, 0, M1);
    cudaEventRecord(e3, 0);
    spmm_csr128h<<<spmmB2, 256>>>(Ah, rp, pe, bh, Bh, M1, M);

    cudaStreamWaitEvent(s2, e3, 0);
    sgemm40<<<g40B1, 256, 0, s2>>>(Bh, W2, Ch, 0, M1);
    cudaEventRecord(e4, s2);

    sgemm40<<<g40B2, 256>>>(Bh, W2, Ch, M1, M);
    cudaStreamWaitEvent(0, e4, 0);    // Ch fully ready

    // ---- Final aggregation + bias + log_softmax ----
    spmm_csr40_lsm<<<spmmBlocksAll, 256>>>(Ch, rp, pe, b2, out, M);
}

// round 15
// speedup vs baseline: 1.0109x; 1.0109x over previous
#include <cuda_runtime.h>
#include <cuda_bf16.h>
#include <cuda_fp16.h>
#include <math.h>
#include <cstdint>

// ---------------------------------------------------------------------------
// GCN: 3x { H = A_sparse @ (H @ W) + b (,ReLU) } -> log_softmax
// N=50000, E=1.6M, 512 -> 128 -> 128 -> 40
// Round 15: R13 base (best: 275.2) + CSR fast path: record staging in hist
//           (L2-warm scatter), single decoupled-lookback scan kernel.
// ---------------------------------------------------------------------------

#define NNODES 50000
#define NEDGES 1600000
#define NFEAT 512
#define NHID  128
#define NCLASS 40

// Scratch (__device__ globals; no allocations allowed)
__device__ __half g_Ah[NNODES * NHID];
__device__ __half g_Bh[NNODES * NHID];
__device__ __half g_Ch[NNODES * NCLASS];
__device__ int    g_cnt[NNODES];
__device__ int    g_cursor[NNODES];
__device__ int    g_rp[NNODES + 1];
__device__ int    g_aggs[256];
__device__ int    g_scanctr;
__device__ uint32_t g_stage[NEDGES];     // packed records in original edge order
__device__ uint32_t g_pe[NEDGES];        // packed records in CSR order
__device__ uint32_t g_W1h[256 * 128];
__device__ uint32_t g_W1l[256 * 128];
__device__ uint32_t g_Whh[64 * 128];
__device__ uint32_t g_Whl[64 * 128];

// ===========================================================================
// helpers
// ===========================================================================
__device__ __forceinline__ void cvt_hilo(float x, float y, uint32_t& hi, uint32_t& lo) {
    __nv_bfloat16 hx = __float2bfloat16(x);
    __nv_bfloat16 hy = __float2bfloat16(y);
    float rx = x - __bfloat162float(hx);
    float ry = y - __bfloat162float(hy);
    __nv_bfloat162 H; H.x = hx; H.y = hy;
    __nv_bfloat162 L; L.x = __float2bfloat16(rx); L.y = __float2bfloat16(ry);
    hi = *reinterpret_cast<uint32_t*>(&H);
    lo = *reinterpret_cast<uint32_t*>(&L);
}

__device__ __forceinline__ void mma16816(float* d, const uint32_t* a, uint32_t b0, uint32_t b1) {
    asm volatile(
        "mma.sync.aligned.m16n8k16.row.col.f32.bf16.bf16.f32 "
        "{%0,%1,%2,%3}, {%4,%5,%6,%7}, {%8,%9}, {%0,%1,%2,%3};"
        : "+f"(d[0]), "+f"(d[1]), "+f"(d[2]), "+f"(d[3])
        : "r"(a[0]), "r"(a[1]), "r"(a[2]), "r"(a[3]), "r"(b0), "r"(b1));
}

__device__ __forceinline__ float4 load4f(const float* p) {
    return *reinterpret_cast<const float4*>(p);
}
__device__ __forceinline__ float4 load4f(const __half* p) {
    uint2 u = *reinterpret_cast<const uint2*>(p);
    float2 a = __half22float2(*reinterpret_cast<__half2*>(&u.x));
    float2 b = __half22float2(*reinterpret_cast<__half2*>(&u.y));
    return make_float4(a.x, a.y, b.x, b.y);
}

__device__ __forceinline__ void unpack_edge(uint32_t rec, int& s, float& w) {
    s = (int)(rec & 0xFFFFu);
    w = __half2float(__ushort_as_half((unsigned short)(rec >> 16)));
}

__device__ __forceinline__ uint32_t pack_edge(int s, float w) {
    return (uint32_t)s | ((uint32_t)__half_as_ushort(__float2half_rn(w)) << 16);
}

// SMEM layout (u32 units). A tiles: [m=128][k2=32 + pad4]. B: [k2=32][n=128+8].
#define AH_OFF 0
#define AL_OFF 4608
#define BH_OFF 9216
#define BL_OFF 13568
#define SM_U32 17920   // 71680 bytes

// ===========================================================================
// Weight pre-pack
// ===========================================================================
__global__ void conv_weights(const float* __restrict__ W1, const float* __restrict__ Wh,
                             uint32_t* __restrict__ W1h, uint32_t* __restrict__ W1l,
                             uint32_t* __restrict__ Whh, uint32_t* __restrict__ Whl) {
    int i = blockIdx.x * 256 + threadIdx.x;
    if (i < 256 * 128) {
        int k2 = i >> 7, n = i & 127;
        float v0 = __ldg(W1 + (size_t)(2 * k2) * 128 + n);
        float v1 = __ldg(W1 + (size_t)(2 * k2 + 1) * 128 + n);
        uint32_t h, lo;
        cvt_hilo(v0, v1, h, lo);
        W1h[i] = h; W1l[i] = lo;
    } else if (i < 256 * 128 + 64 * 128) {
        int j = i - 256 * 128;
        int k2 = j >> 7, n = j & 127;
        float v0 = __ldg(Wh + (size_t)(2 * k2) * 128 + n);
        float v1 = __ldg(Wh + (size_t)(2 * k2 + 1) * 128 + n);
        uint32_t h, lo;
        cvt_hilo(v0, v1, h, lo);
        Whh[j] = h; Whl[j] = lo;
    }
}

// ===========================================================================
// mma.sync GEMM: C[M,128] = A[M,K] @ W[K,128]; A fp32/fp16; W pre-packed.
// ===========================================================================
template <typename TIn>
__global__ void __launch_bounds__(256, 2) mma_gemm128(
    const TIn* __restrict__ A,
    const uint32_t* __restrict__ Wph, const uint32_t* __restrict__ Wpl,
    __half* __restrict__ C, int M, int K) {
    extern __shared__ uint32_t sm[];
    uint32_t* AH = sm + AH_OFF;
    uint32_t* AL = sm + AL_OFF;
    uint32_t* BH = sm + BH_OFF;
    uint32_t* BL = sm + BL_OFF;

    const int t = threadIdx.x;
    const int lane = t & 31;
    const int wid = t >> 5;
    const int warpM = wid >> 1;
    const int warpN = wid & 1;
    const int row0 = blockIdx.x * 128;

    float acc[2][8][4];
#pragma unroll
    for (int mt = 0; mt < 2; mt++)
#pragma unroll
        for (int nt = 0; nt < 8; nt++)
#pragma unroll
            for (int e = 0; e < 4; e++) acc[mt][nt][e] = 0.f;

    const int r4 = lane >> 2;
    const int q4 = lane & 3;

    const int nChunks = K >> 6;
    for (int c = 0; c < nChunks; c++) {
        const int k0 = c << 6;
        const int k0h = c << 5;
        __syncthreads();

#pragma unroll
        for (int l = 0; l < 8; l++) {
            int q = t + l * 256;
            int m = q >> 4;
            int c4 = q & 15;
            float4 v = make_float4(0.f, 0.f, 0.f, 0.f);
            if (row0 + m < M)
                v = load4f(A + (size_t)(row0 + m) * K + k0 + c4 * 4);
            uint32_t h0, l0, h1, l1;
            cvt_hilo(v.x, v.y, h0, l0);
            cvt_hilo(v.z, v.w, h1, l1);
            int base = m * 36 + c4 * 2;
            AH[base] = h0; AH[base + 1] = h1;
            AL[base] = l0; AL[base + 1] = l1;
        }
#pragma unroll
        for (int l = 0; l < 4; l++) {
            int q = t + l * 256;
            int k2 = q >> 5;
            int n4 = q & 31;
            size_t goff = (size_t)(k0h + k2) * 128 + n4 * 4;
            uint4 vh = __ldg(reinterpret_cast<const uint4*>(Wph + goff));
            uint4 vl = __ldg(reinterpret_cast<const uint4*>(Wpl + goff));
            *reinterpret_cast<uint4*>(&BH[k2 * 136 + n4 * 4]) = vh;
            *reinterpret_cast<uint4*>(&BL[k2 * 136 + n4 * 4]) = vl;
        }
        __syncthreads();

#pragma unroll
        for (int k8 = 0; k8 < 4; k8++) {
            int klo = k8 * 8 + q4;
            uint32_t ah[2][4], al[2][4];
#pragma unroll
            for (int mt = 0; mt < 2; mt++) {
                int base = (warpM * 32 + mt * 16 + r4) * 36;
                ah[mt][0] = AH[base + klo];
                ah[mt][1] = AH[base + 8 * 36 + klo];
                ah[mt][2] = AH[base + klo + 4];
                ah[mt][3] = AH[base + 8 * 36 + klo + 4];
                al[mt][0] = AL[base + klo];
                al[mt][1] = AL[base + 8 * 36 + klo];
                al[mt][2] = AL[base + klo + 4];
                al[mt][3] = AL[base + 8 * 36 + klo + 4];
            }
#pragma unroll
            for (int nt = 0; nt < 8; nt++) {
                int nB = warpN * 64 + nt * 8 + r4;
                uint32_t bh0 = BH[klo * 136 + nB];
                uint32_t bh1 = BH[(klo + 4) * 136 + nB];
                uint32_t bl0 = BL[klo * 136 + nB];
                uint32_t bl1 = BL[(klo + 4) * 136 + nB];
#pragma unroll
                for (int mt = 0; mt < 2; mt++) {
                    mma16816(acc[mt][nt], ah[mt], bh0, bh1);
                    mma16816(acc[mt][nt], ah[mt], bl0, bl1);
                    mma16816(acc[mt][nt], al[mt], bh0, bh1);
                }
            }
        }
    }

#pragma unroll
    for (int mt = 0; mt < 2; mt++) {
        int rowA = row0 + warpM * 32 + mt * 16 + r4;
        int rowB = rowA + 8;
#pragma unroll
        for (int nt = 0; nt < 8; nt++) {
            int col = warpN * 64 + nt * 8 + q4 * 2;
            if (rowA < M)
                *reinterpret_cast<__half2*>(C + (size_t)rowA * 128 + col) =
                    __floats2half2_rn(acc[mt][nt][0], acc[mt][nt][1]);
            if (rowB < M)
                *reinterpret_cast<__half2*>(C + (size_t)rowB * 128 + col) =
                    __floats2half2_rn(acc[mt][nt][2], acc[mt][nt][3]);
        }
    }
}

// ===========================================================================
// CSR build: zero(+ctr) -> hist+stage -> lookback scan -> scatter (L2-warm)
// ===========================================================================
__global__ void zero_int4(int4* p, int n4, int* ctr) {
    int i = blockIdx.x * blockDim.x + threadIdx.x;
    if (i < n4) p[i] = make_int4(0, 0, 0, 0);
    if (i == 0) *ctr = 0;
}

// Histogram + stage packed records coalesced (warms L2 for scatter).
__global__ void hist_stage(const int4* __restrict__ src4, const int4* __restrict__ dst4,
                           const float4* __restrict__ w4, int* __restrict__ cnt,
                           uint4* __restrict__ stage, int n4) {
    int e = blockIdx.x * blockDim.x + threadIdx.x;
    if (e >= n4) return;
    int4 s = __ldg(src4 + e);
    int4 d = __ldg(dst4 + e);
    float4 ww = __ldg(w4 + e);
    uint4 r;
    r.x = pack_edge(s.x, ww.x);
    r.y = pack_edge(s.y, ww.y);
    r.z = pack_edge(s.z, ww.z);
    r.w = pack_edge(s.w, ww.w);
    stage[e] = r;
    atomicAdd(&cnt[d.x], 1);
    atomicAdd(&cnt[d.y], 1);
    atomicAdd(&cnt[d.z], 1);
    atomicAdd(&cnt[d.w], 1);
}

// Single-kernel scan: local scan + publish aggregate + device-wide wait +
// offset apply. Grid (196 blocks) is far below one wave -> all resident -> safe.
__global__ void scan_lookback(const int* __restrict__ cnt, int* __restrict__ rp,
                              int* __restrict__ cursor, int* __restrict__ ctr,
                              int* __restrict__ aggs, int n, int nb, int nE) {
    __shared__ int wsum[8];
    __shared__ int red[8];
    const int lane = threadIdx.x & 31;
    const int wid  = threadIdx.x >> 5;
    int i = blockIdx.x * 256 + threadIdx.x;
    int v = (i < n) ? cnt[i] : 0;

    int incl = v;
#pragma unroll
    for (int o = 1; o < 32; o <<= 1) {
        int tt = __shfl_up_sync(0xffffffffu, incl, o);
        if (lane >= o) incl += tt;
    }
    if (lane == 31) wsum[wid] = incl;
    __syncthreads();
    if (wid == 0) {
        int s = (lane < 8) ? wsum[lane] : 0;
#pragma unroll
        for (int o = 1; o < 8; o <<= 1) {
            int tt = __shfl_up_sync(0xffffffffu, s, o);
            if (lane >= o) s += tt;
        }
        if (lane < 8) wsum[lane] = s;
    }
    __syncthreads();
    int excl = (wid ? wsum[wid - 1] : 0) + incl - v;
    int total = wsum[7];

    // publish aggregate, then device-wide wait for all blocks
    if (threadIdx.x == 0) {
        aggs[blockIdx.x] = total;
        __threadfence();
        atomicAdd(ctr, 1);
        while (atomicAdd(ctr, 0) < nb) { }
    }
    __syncthreads();
    __threadfence();

    // offset = sum of aggs[0 .. blockIdx.x)
    int a = (threadIdx.x < nb && threadIdx.x < blockIdx.x) ? aggs[threadIdx.x] : 0;
#pragma unroll
    for (int o = 16; o > 0; o >>= 1) a += __shfl_xor_sync(0xffffffffu, a, o);
    if (lane == 0) red[wid] = a;
    __syncthreads();
    if (threadIdx.x == 0) {
        int s = 0;
#pragma unroll
        for (int j = 0; j < 8; j++) s += red[j];
        red[0] = s;
    }
    __syncthreads();
    int off = red[0];
    if (i < n) {
        int val = excl + off;
        rp[i] = val;
        cursor[i] = val;
    }
    if (blockIdx.x == 0 && threadIdx.x == 0) rp[n] = nE;
}

// Scatter from staged records (L2-warm) + edst (L2-warm).
__global__ void scatter_staged(const uint4* __restrict__ stage, const int4* __restrict__ dst4,
                               int* __restrict__ cursor, uint32_t* __restrict__ pe,
                               int n4,
                               const int* __restrict__ src, const int* __restrict__ dst,
                               const float* __restrict__ w, int nE) {
    int e = blockIdx.x * blockDim.x + threadIdx.x;
    if (e < n4) {
        uint4 r = __ldg(stage + e);
        int4 d = __ldg(dst4 + e);
        int p0 = atomicAdd(&cursor[d.x], 1);
        pe[p0] = r.x;
        int p1 = atomicAdd(&cursor[d.y], 1);
        pe[p1] = r.y;
        int p2 = atomicAdd(&cursor[d.z], 1);
        pe[p2] = r.z;
        int p3 = atomicAdd(&cursor[d.w], 1);
        pe[p3] = r.w;
    } else if (e == n4) {
        // scalar tail (nE % 4 edges)
        for (int k = n4 * 4; k < nE; k++) {
            int dd = __ldg(dst + k);
            int pos = atomicAdd(&cursor[dd], 1);
            pe[pos] = pack_edge(__ldg(src + k), __ldg(w + k));
        }
    }
}

// ===========================================================================
// GEMM3: C[M,40] = H[M,128] @ W2[128,40]; fp16 in, fp16 out; fp32 math.
// ===========================================================================
__global__ void sgemm40(const __half* __restrict__ H, const float* __restrict__ W,
                        __half* __restrict__ C, int M) {
    __shared__ float Ht[32][132];
    __shared__ float Ws[128][40];

    const int t = threadIdx.x;
    const int row0 = blockIdx.x * 32;

#pragma unroll
    for (int l = 0; l < 4; l++) {
        int q = t + l * 256;
        int r = q >> 5;
        int c4 = q & 31;
        float4 v = make_float4(0.f, 0.f, 0.f, 0.f);
        if (row0 + r < M)
            v = load4f(H + (size_t)(row0 + r) * 128 + c4 * 4);
        *reinterpret_cast<float4*>(&Ht[r][c4 * 4]) = v;
    }
#pragma unroll
    for (int l = 0; l < 20; l++) {
        int q = t + l * 256;
        Ws[q / 40][q % 40] = W[q];
    }
    __syncthreads();

    const int r = t >> 3;
    const int cg = t & 7;
    float acc[5] = {0.f, 0.f, 0.f, 0.f, 0.f};
#pragma unroll 8
    for (int k = 0; k < 128; k++) {
        float h = Ht[r][k];
#pragma unroll
        for (int j = 0; j < 5; j++)
            acc[j] = fmaf(h, Ws[k][cg * 5 + j], acc[j]);
    }
    int grow = row0 + r;
    if (grow < M) {
#pragma unroll
        for (int j = 0; j < 5; j++)
            C[(size_t)grow * 40 + cg * 5 + j] = __float2half_rn(acc[j]);
    }
}

// ===========================================================================
// Gather SpMM (feat=128, fp16 in, fp32 accum, fp16 out) + bias + ReLU
// ===========================================================================
__device__ __forceinline__ void acc4h(float& ax, float& ay, float& az, float& aw,
                                      float w, uint2 r) {
    float2 a01 = __half22float2(*reinterpret_cast<__half2*>(&r.x));
    float2 a23 = __half22float2(*reinterpret_cast<__half2*>(&r.y));
    ax = fmaf(w, a01.x, ax); ay = fmaf(w, a01.y, ay);
    az = fmaf(w, a23.x, az); aw = fmaf(w, a23.y, aw);
}

__global__ void __launch_bounds__(256) spmm_csr128h(
    const __half* __restrict__ H, const int* __restrict__ rp,
    const uint32_t* __restrict__ pe, const float* __restrict__ bias,
    __half* __restrict__ out, int M) {
    int row = blockIdx.x * 8 + (threadIdx.x >> 5);
    int lane = threadIdx.x & 31;
    if (row >= M) return;
    int p  = __ldg(rp + row);
    int pend = __ldg(rp + row + 1);

    const char* Hb = reinterpret_cast<const char*>(H) + lane * 8;
    float ax = 0.f, ay = 0.f, az = 0.f, aw = 0.f;

    for (; p + 4 <= pend; p += 4) {
        uint32_t e0 = __ldg(pe + p + 0), e1 = __ldg(pe + p + 1);
        uint32_t e2 = __ldg(pe + p + 2), e3 = __ldg(pe + p + 3);
        int s0, s1, s2, s3;
        float w0, w1, w2, w3;
        unpack_edge(e0, s0, w0);
        unpack_edge(e1, s1, w1);
        unpack_edge(e2, s2, w2);
        unpack_edge(e3, s3, w3);
        uint2 r0 = *reinterpret_cast<const uint2*>(Hb + (size_t)s0 * 256);
        uint2 r1 = *reinterpret_cast<const uint2*>(Hb + (size_t)s1 * 256);
        uint2 r2 = *reinterpret_cast<const uint2*>(Hb + (size_t)s2 * 256);
        uint2 r3 = *reinterpret_cast<const uint2*>(Hb + (size_t)s3 * 256);
        acc4h(ax, ay, az, aw, w0, r0);
        acc4h(ax, ay, az, aw, w1, r1);
        acc4h(ax, ay, az, aw, w2, r2);
        acc4h(ax, ay, az, aw, w3, r3);
    }
    for (; p < pend; p++) {
        int s;
        float w;
        unpack_edge(__ldg(pe + p), s, w);
        uint2 r0 = *reinterpret_cast<const uint2*>(Hb + (size_t)s * 256);
        acc4h(ax, ay, az, aw, w, r0);
    }

    float4 b4 = *reinterpret_cast<const float4*>(bias + lane * 4);
    __half2 o01 = __floats2half2_rn(fmaxf(ax + b4.x, 0.f), fmaxf(ay + b4.y, 0.f));
    __half2 o23 = __floats2half2_rn(fmaxf(az + b4.z, 0.f), fmaxf(aw + b4.w, 0.f));
    uint2 st;
    st.x = *reinterpret_cast<uint32_t*>(&o01);
    st.y = *reinterpret_cast<uint32_t*>(&o23);
    *reinterpret_cast<uint2*>(reinterpret_cast<char*>(out) + (size_t)row * 256 + lane * 8) = st;
}

// ===========================================================================
// Gather SpMM (feat=40, fp16 logits, fp32 accum) + bias + log_softmax
// ===========================================================================
__global__ void __launch_bounds__(256) spmm_csr40_lsm(
    const __half* __restrict__ C, const int* __restrict__ rp,
    const uint32_t* __restrict__ pe, const float* __restrict__ b,
    float* __restrict__ out, int M) {
    int row = blockIdx.x * 8 + (threadIdx.x >> 5);
    int lane = threadIdx.x & 31;
    if (row >= M) return;
    int p  = __ldg(rp + row);
    int pend = __ldg(rp + row + 1);

    float a0 = 0.f, a1 = 0.f;
    for (; p + 2 <= pend; p += 2) {
        int s0, s1;
        float w0, w1;
        unpack_edge(__ldg(pe + p), s0, w0);
        unpack_edge(__ldg(pe + p + 1), s1, w1);
        const __half* c0 = C + (size_t)s0 * 40;
        const __half* c1 = C + (size_t)s1 * 40;
        float x0 = __half2float(__ldg(c0 + lane));
        float x1 = __half2float(__ldg(c1 + lane));
        float y0 = (lane < 8) ? __half2float(__ldg(c0 + 32 + lane)) : 0.f;
        float y1 = (lane < 8) ? __half2float(__ldg(c1 + 32 + lane)) : 0.f;
        a0 = fmaf(w0, x0, a0); a0 = fmaf(w1, x1, a0);
        a1 = fmaf(w0, y0, a1); a1 = fmaf(w1, y1, a1);
    }
    if (p < pend) {
        int s;
        float w;
        unpack_edge(__ldg(pe + p), s, w);
        const __half* c0 = C + (size_t)s * 40;
        a0 = fmaf(w, __half2float(__ldg(c0 + lane)), a0);
        if (lane < 8) a1 = fmaf(w, __half2float(__ldg(c0 + 32 + lane)), a1);
    }

    float v0 = a0 + __ldg(b + lane);
    float v1 = (lane < 8) ? (a1 + __ldg(b + 32 + lane)) : -INFINITY;

    float m = fmaxf(v0, v1);
#pragma unroll
    for (int o = 16; o > 0; o >>= 1) m = fmaxf(m, __shfl_xor_sync(0xffffffffu, m, o));
    float s = __expf(v0 - m) + ((lane < 8) ? __expf(v1 - m) : 0.f);
#pragma unroll
    for (int o = 16; o > 0; o >>= 1) s += __shfl_xor_sync(0xffffffffu, s, o);
    float ls = m + __logf(s);

    out[(size_t)row * 40 + lane] = v0 - ls;
    if (lane < 8) out[(size_t)row * 40 + 32 + lane] = v1 - ls;
}

// ===========================================================================
extern "C" void kernel_launch(void* const* d_in, const int* in_sizes, int n_in,
                              void* d_out, int out_size) {
    const float* x    = (const float*)d_in[0];
    const int*   esrc = (const int*)  d_in[1];
    const int*   edst = (const int*)  d_in[2];
    const float* ew   = (const float*)d_in[3];
    const float* W1   = (const float*)d_in[4];
    const float* b1   = (const float*)d_in[5];
    const float* Wh   = (const float*)d_in[6];
    const float* bh   = (const float*)d_in[7];
    const float* W2   = (const float*)d_in[8];
    const float* b2   = (const float*)d_in[9];
    float* out = (float*)d_out;

    const int M  = in_sizes[0] / NFEAT;   // 50000
    const int nE = in_sizes[1];           // 1600000

    __half *Ah, *Bh, *Ch;
    int *cnt, *cursor, *rp, *aggs, *ctr;
    uint32_t *pe, *stage;
    uint32_t *W1h, *W1l, *Whh, *Whl;
    cudaGetSymbolAddress((void**)&Ah, g_Ah);
    cudaGetSymbolAddress((void**)&Bh, g_Bh);
    cudaGetSymbolAddress((void**)&Ch, g_Ch);
    cudaGetSymbolAddress((void**)&cnt, g_cnt);
    cudaGetSymbolAddress((void**)&cursor, g_cursor);
    cudaGetSymbolAddress((void**)&rp, g_rp);
    cudaGetSymbolAddress((void**)&aggs, g_aggs);
    cudaGetSymbolAddress((void**)&ctr, g_scanctr);
    cudaGetSymbolAddress((void**)&pe, g_pe);
    cudaGetSymbolAddress((void**)&stage, g_stage);
    cudaGetSymbolAddress((void**)&W1h, g_W1h);
    cudaGetSymbolAddress((void**)&W1l, g_W1l);
    cudaGetSymbolAddress((void**)&Whh, g_Whh);
    cudaGetSymbolAddress((void**)&Whl, g_Whl);

    static cudaStream_t s2 = nullptr;
    static cudaEvent_t evF = nullptr, evJ = nullptr;
    if (!s2) {
        cudaStreamCreateWithFlags(&s2, cudaStreamNonBlocking);
        cudaEventCreateWithFlags(&evF, cudaEventDisableTiming);
        cudaEventCreateWithFlags(&evJ, cudaEventDisableTiming);
        cudaFuncSetAttribute(mma_gemm128<float>,
                             cudaFuncAttributeMaxDynamicSharedMemorySize, SM_U32 * 4);
        cudaFuncSetAttribute(mma_gemm128<__half>,
                             cudaFuncAttributeMaxDynamicSharedMemorySize, SM_U32 * 4);
    }

    const int nb = (M + 255) / 256;           // 196
    const int gemmBlocks = (M + 127) / 128;   // 391
    const int spmmBlocks = (M + 7) / 8;
    const int nE4 = nE / 4;

    // ---- Fork: CSR build on s2, weight pack + layer-1 GEMM on main ----
    cudaEventRecord(evF, 0);
    cudaStreamWaitEvent(s2, evF, 0);

    zero_int4<<<(M / 4 + 255) / 256, 256, 0, s2>>>((int4*)cnt, (M + 3) / 4, ctr);
    hist_stage<<<(nE4 + 255) / 256, 256, 0, s2>>>(
        (const int4*)esrc, (const int4*)edst, (const float4*)ew, cnt, (uint4*)stage, nE4);
    scan_lookback<<<nb, 256, 0, s2>>>(cnt, rp, cursor, ctr, aggs, M, nb, nE);
    scatter_staged<<<(nE4 + 1 + 255) / 256, 256, 0, s2>>>(
        (const uint4*)stage, (const int4*)edst, cursor, pe, nE4, esrc, edst, ew, nE);
    cudaEventRecord(evJ, s2);

    conv_weights<<<160, 256>>>(W1, Wh, W1h, W1l, Whh, Whl);
    mma_gemm128<float><<<gemmBlocks, 256, SM_U32 * 4>>>(x, W1h, W1l, Ah, M, NFEAT);

    cudaStreamWaitEvent(0, evJ, 0);   // join

    // Layer 1 aggregation (fp16 out)
    spmm_csr128h<<<spmmBlocks, 256>>>(Ah, rp, pe, b1, Bh, M);

    // Layer 2 (fp16 in)
    mma_gemm128<__half><<<gemmBlocks, 256, SM_U32 * 4>>>(Bh, Whh, Whl, Ah, M, NHID);
    spmm_csr128h<<<spmmBlocks, 256>>>(Ah, rp, pe, bh, Bh, M);

    // Layer 3 + log_softmax
    sgemm40<<<(M + 31) / 32, 256>>>(Bh, W2, Ch, M);
    spmm_csr40_lsm<<<spmmBlocks, 256>>>(Ch, rp, pe, b2, out, M);
}

// round 16
// speedup vs baseline: 1.0325x; 1.0213x over previous
#include <cuda_runtime.h>
#include <cuda_bf16.h>
#include <cuda_fp16.h>
#include <math.h>
#include <cstdint>

// ---------------------------------------------------------------------------
// GCN: 3x { H = A_sparse @ (H @ W) + b (,ReLU) } -> log_softmax
// N=50000, E=1.6M, 512 -> 128 -> 128 -> 40
// Round 16: R15 base + packed cvt.rn.bf16x2.f32 hi/lo conversion (6 inst/pair
//           vs ~11) -- GEMM1 A-stage is the fork-critical-path hot spot.
// ---------------------------------------------------------------------------

#define NNODES 50000
#define NEDGES 1600000
#define NFEAT 512
#define NHID  128
#define NCLASS 40

// Scratch (__device__ globals; no allocations allowed)
__device__ __half g_Ah[NNODES * NHID];
__device__ __half g_Bh[NNODES * NHID];
__device__ __half g_Ch[NNODES * NCLASS];
__device__ int    g_cnt[NNODES];
__device__ int    g_cursor[NNODES];
__device__ int    g_rp[NNODES + 1];
__device__ int    g_aggs[256];
__device__ int    g_scanctr;
__device__ uint32_t g_stage[NEDGES];     // packed records in original edge order
__device__ uint32_t g_pe[NEDGES];        // packed records in CSR order
__device__ uint32_t g_W1h[256 * 128];
__device__ uint32_t g_W1l[256 * 128];
__device__ uint32_t g_Whh[64 * 128];
__device__ uint32_t g_Whl[64 * 128];

// ===========================================================================
// helpers
// ===========================================================================
// Packed hi/lo split: hi = bf16x2(x,y); lo = bf16x2 of residuals.
// cvt.rn.bf16x2.f32 d, a, b packs: d.lo = bf16(b), d.hi = bf16(a).
__device__ __forceinline__ void cvt_hilo(float x, float y, uint32_t& hi, uint32_t& lo) {
    uint32_t h;
    asm("cvt.rn.bf16x2.f32 %0, %1, %2;" : "=r"(h) : "f"(y), "f"(x));
    float hx = __uint_as_float(h << 16);
    float hy = __uint_as_float(h & 0xFFFF0000u);
    float rx = x - hx;
    float ry = y - hy;
    uint32_t l;
    asm("cvt.rn.bf16x2.f32 %0, %1, %2;" : "=r"(l) : "f"(ry), "f"(rx));
    hi = h; lo = l;
}

__device__ __forceinline__ void mma16816(float* d, const uint32_t* a, uint32_t b0, uint32_t b1) {
    asm volatile(
        "mma.sync.aligned.m16n8k16.row.col.f32.bf16.bf16.f32 "
        "{%0,%1,%2,%3}, {%4,%5,%6,%7}, {%8,%9}, {%0,%1,%2,%3};"
        : "+f"(d[0]), "+f"(d[1]), "+f"(d[2]), "+f"(d[3])
        : "r"(a[0]), "r"(a[1]), "r"(a[2]), "r"(a[3]), "r"(b0), "r"(b1));
}

__device__ __forceinline__ float4 load4f(const float* p) {
    return *reinterpret_cast<const float4*>(p);
}
__device__ __forceinline__ float4 load4f(const __half* p) {
    uint2 u = *reinterpret_cast<const uint2*>(p);
    float2 a = __half22float2(*reinterpret_cast<__half2*>(&u.x));
    float2 b = __half22float2(*reinterpret_cast<__half2*>(&u.y));
    return make_float4(a.x, a.y, b.x, b.y);
}

__device__ __forceinline__ void unpack_edge(uint32_t rec, int& s, float& w) {
    s = (int)(rec & 0xFFFFu);
    w = __half2float(__ushort_as_half((unsigned short)(rec >> 16)));
}

__device__ __forceinline__ uint32_t pack_edge(int s, float w) {
    return (uint32_t)s | ((uint32_t)__half_as_ushort(__float2half_rn(w)) << 16);
}

// SMEM layout (u32 units). A tiles: [m=128][k2=32 + pad4]. B: [k2=32][n=128+8].
#define AH_OFF 0
#define AL_OFF 4608
#define BH_OFF 9216
#define BL_OFF 13568
#define SM_U32 17920   // 71680 bytes

// ===========================================================================
// Weight pre-pack
// ===========================================================================
__global__ void conv_weights(const float* __restrict__ W1, const float* __restrict__ Wh,
                             uint32_t* __restrict__ W1h, uint32_t* __restrict__ W1l,
                             uint32_t* __restrict__ Whh, uint32_t* __restrict__ Whl) {
    int i = blockIdx.x * 256 + threadIdx.x;
    if (i < 256 * 128) {
        int k2 = i >> 7, n = i & 127;
        float v0 = __ldg(W1 + (size_t)(2 * k2) * 128 + n);
        float v1 = __ldg(W1 + (size_t)(2 * k2 + 1) * 128 + n);
        uint32_t h, lo;
        cvt_hilo(v0, v1, h, lo);
        W1h[i] = h; W1l[i] = lo;
    } else if (i < 256 * 128 + 64 * 128) {
        int j = i - 256 * 128;
        int k2 = j >> 7, n = j & 127;
        float v0 = __ldg(Wh + (size_t)(2 * k2) * 128 + n);
        float v1 = __ldg(Wh + (size_t)(2 * k2 + 1) * 128 + n);
        uint32_t h, lo;
        cvt_hilo(v0, v1, h, lo);
        Whh[j] = h; Whl[j] = lo;
    }
}

// ===========================================================================
// mma.sync GEMM: C[M,128] = A[M,K] @ W[K,128]; A fp32/fp16; W pre-packed.
// ===========================================================================
template <typename TIn>
__global__ void __launch_bounds__(256, 2) mma_gemm128(
    const TIn* __restrict__ A,
    const uint32_t* __restrict__ Wph, const uint32_t* __restrict__ Wpl,
    __half* __restrict__ C, int M, int K) {
    extern __shared__ uint32_t sm[];
    uint32_t* AH = sm + AH_OFF;
    uint32_t* AL = sm + AL_OFF;
    uint32_t* BH = sm + BH_OFF;
    uint32_t* BL = sm + BL_OFF;

    const int t = threadIdx.x;
    const int lane = t & 31;
    const int wid = t >> 5;
    const int warpM = wid >> 1;
    const int warpN = wid & 1;
    const int row0 = blockIdx.x * 128;

    float acc[2][8][4];
#pragma unroll
    for (int mt = 0; mt < 2; mt++)
#pragma unroll
        for (int nt = 0; nt < 8; nt++)
#pragma unroll
            for (int e = 0; e < 4; e++) acc[mt][nt][e] = 0.f;

    const int r4 = lane >> 2;
    const int q4 = lane & 3;

    const int nChunks = K >> 6;
    for (int c = 0; c < nChunks; c++) {
        const int k0 = c << 6;
        const int k0h = c << 5;
        __syncthreads();

#pragma unroll
        for (int l = 0; l < 8; l++) {
            int q = t + l * 256;
            int m = q >> 4;
            int c4 = q & 15;
            float4 v = make_float4(0.f, 0.f, 0.f, 0.f);
            if (row0 + m < M)
                v = load4f(A + (size_t)(row0 + m) * K + k0 + c4 * 4);
            uint32_t h0, l0, h1, l1;
            cvt_hilo(v.x, v.y, h0, l0);
            cvt_hilo(v.z, v.w, h1, l1);
            int base = m * 36 + c4 * 2;
            AH[base] = h0; AH[base + 1] = h1;
            AL[base] = l0; AL[base + 1] = l1;
        }
#pragma unroll
        for (int l = 0; l < 4; l++) {
            int q = t + l * 256;
            int k2 = q >> 5;
            int n4 = q & 31;
            size_t goff = (size_t)(k0h + k2) * 128 + n4 * 4;
            uint4 vh = __ldg(reinterpret_cast<const uint4*>(Wph + goff));
            uint4 vl = __ldg(reinterpret_cast<const uint4*>(Wpl + goff));
            *reinterpret_cast<uint4*>(&BH[k2 * 136 + n4 * 4]) = vh;
            *reinterpret_cast<uint4*>(&BL[k2 * 136 + n4 * 4]) = vl;
        }
        __syncthreads();

#pragma unroll
        for (int k8 = 0; k8 < 4; k8++) {
            int klo = k8 * 8 + q4;
            uint32_t ah[2][4], al[2][4];
#pragma unroll
            for (int mt = 0; mt < 2; mt++) {
                int base = (warpM * 32 + mt * 16 + r4) * 36;
                ah[mt][0] = AH[base + klo];
                ah[mt][1] = AH[base + 8 * 36 + klo];
                ah[mt][2] = AH[base + klo + 4];
                ah[mt][3] = AH[base + 8 * 36 + klo + 4];
                al[mt][0] = AL[base + klo];
                al[mt][1] = AL[base + 8 * 36 + klo];
                al[mt][2] = AL[base + klo + 4];
                al[mt][3] = AL[base + 8 * 36 + klo + 4];
            }
#pragma unroll
            for (int nt = 0; nt < 8; nt++) {
                int nB = warpN * 64 + nt * 8 + r4;
                uint32_t bh0 = BH[klo * 136 + nB];
                uint32_t bh1 = BH[(klo + 4) * 136 + nB];
                uint32_t bl0 = BL[klo * 136 + nB];
                uint32_t bl1 = BL[(klo + 4) * 136 + nB];
#pragma unroll
                for (int mt = 0; mt < 2; mt++) {
                    mma16816(acc[mt][nt], ah[mt], bh0, bh1);
                    mma16816(acc[mt][nt], ah[mt], bl0, bl1);
                    mma16816(acc[mt][nt], al[mt], bh0, bh1);
                }
            }
        }
    }

#pragma unroll
    for (int mt = 0; mt < 2; mt++) {
        int rowA = row0 + warpM * 32 + mt * 16 + r4;
        int rowB = rowA + 8;
#pragma unroll
        for (int nt = 0; nt < 8; nt++) {
            int col = warpN * 64 + nt * 8 + q4 * 2;
            if (rowA < M)
                *reinterpret_cast<__half2*>(C + (size_t)rowA * 128 + col) =
                    __floats2half2_rn(acc[mt][nt][0], acc[mt][nt][1]);
            if (rowB < M)
                *reinterpret_cast<__half2*>(C + (size_t)rowB * 128 + col) =
                    __floats2half2_rn(acc[mt][nt][2], acc[mt][nt][3]);
        }
    }
}

// ===========================================================================
// CSR build: zero(+ctr) -> hist+stage -> lookback scan -> scatter
// ===========================================================================
__global__ void zero_int4(int4* p, int n4, int* ctr) {
    int i = blockIdx.x * blockDim.x + threadIdx.x;
    if (i < n4) p[i] = make_int4(0, 0, 0, 0);
    if (i == 0) *ctr = 0;
}

__global__ void hist_stage(const int4* __restrict__ src4, const int4* __restrict__ dst4,
                           const float4* __restrict__ w4, int* __restrict__ cnt,
                           uint4* __restrict__ stage, int n4) {
    int e = blockIdx.x * blockDim.x + threadIdx.x;
    if (e >= n4) return;
    int4 s = __ldg(src4 + e);
    int4 d = __ldg(dst4 + e);
    float4 ww = __ldg(w4 + e);
    uint4 r;
    r.x = pack_edge(s.x, ww.x);
    r.y = pack_edge(s.y, ww.y);
    r.z = pack_edge(s.z, ww.z);
    r.w = pack_edge(s.w, ww.w);
    stage[e] = r;
    atomicAdd(&cnt[d.x], 1);
    atomicAdd(&cnt[d.y], 1);
    atomicAdd(&cnt[d.z], 1);
    atomicAdd(&cnt[d.w], 1);
}

__global__ void scan_lookback(const int* __restrict__ cnt, int* __restrict__ rp,
                              int* __restrict__ cursor, int* __restrict__ ctr,
                              int* __restrict__ aggs, int n, int nb, int nE) {
    __shared__ int wsum[8];
    __shared__ int red[8];
    const int lane = threadIdx.x & 31;
    const int wid  = threadIdx.x >> 5;
    int i = blockIdx.x * 256 + threadIdx.x;
    int v = (i < n) ? cnt[i] : 0;

    int incl = v;
#pragma unroll
    for (int o = 1; o < 32; o <<= 1) {
        int tt = __shfl_up_sync(0xffffffffu, incl, o);
        if (lane >= o) incl += tt;
    }
    if (lane == 31) wsum[wid] = incl;
    __syncthreads();
    if (wid == 0) {
        int s = (lane < 8) ? wsum[lane] : 0;
#pragma unroll
        for (int o = 1; o < 8; o <<= 1) {
            int tt = __shfl_up_sync(0xffffffffu, s, o);
            if (lane >= o) s += tt;
        }
        if (lane < 8) wsum[lane] = s;
    }
    __syncthreads();
    int excl = (wid ? wsum[wid - 1] : 0) + incl - v;
    int total = wsum[7];

    if (threadIdx.x == 0) {
        aggs[blockIdx.x] = total;
        __threadfence();
        atomicAdd(ctr, 1);
        while (atomicAdd(ctr, 0) < nb) { }
    }
    __syncthreads();
    __threadfence();

    int a = (threadIdx.x < nb && threadIdx.x < blockIdx.x) ? aggs[threadIdx.x] : 0;
#pragma unroll
    for (int o = 16; o > 0; o >>= 1) a += __shfl_xor_sync(0xffffffffu, a, o);
    if (lane == 0) red[wid] = a;
    __syncthreads();
    if (threadIdx.x == 0) {
        int s = 0;
#pragma unroll
        for (int j = 0; j < 8; j++) s += red[j];
        red[0] = s;
    }
    __syncthreads();
    int off = red[0];
    if (i < n) {
        int val = excl + off;
        rp[i] = val;
        cursor[i] = val;
    }
    if (blockIdx.x == 0 && threadIdx.x == 0) rp[n] = nE;
}

__global__ void scatter_staged(const uint4* __restrict__ stage, const int4* __restrict__ dst4,
                               int* __restrict__ cursor, uint32_t* __restrict__ pe,
                               int n4,
                               const int* __restrict__ src, const int* __restrict__ dst,
                               const float* __restrict__ w, int nE) {
    int e = blockIdx.x * blockDim.x + threadIdx.x;
    if (e < n4) {
        uint4 r = __ldg(stage + e);
        int4 d = __ldg(dst4 + e);
        int p0 = atomicAdd(&cursor[d.x], 1);
        pe[p0] = r.x;
        int p1 = atomicAdd(&cursor[d.y], 1);
        pe[p1] = r.y;
        int p2 = atomicAdd(&cursor[d.z], 1);
        pe[p2] = r.z;
        int p3 = atomicAdd(&cursor[d.w], 1);
        pe[p3] = r.w;
    } else if (e == n4) {
        for (int k = n4 * 4; k < nE; k++) {
            int dd = __ldg(dst + k);
            int pos = atomicAdd(&cursor[dd], 1);
            pe[pos] = pack_edge(__ldg(src + k), __ldg(w + k));
        }
    }
}

// ===========================================================================
// GEMM3: C[M,40] = H[M,128] @ W2[128,40]; fp16 in, fp16 out; fp32 math.
// ===========================================================================
__global__ void sgemm40(const __half* __restrict__ H, const float* __restrict__ W,
                        __half* __restrict__ C, int M) {
    __shared__ float Ht[32][132];
    __shared__ float Ws[128][40];

    const int t = threadIdx.x;
    const int row0 = blockIdx.x * 32;

#pragma unroll
    for (int l = 0; l < 4; l++) {
        int q = t + l * 256;
        int r = q >> 5;
        int c4 = q & 31;
        float4 v = make_float4(0.f, 0.f, 0.f, 0.f);
        if (row0 + r < M)
            v = load4f(H + (size_t)(row0 + r) * 128 + c4 * 4);
        *reinterpret_cast<float4*>(&Ht[r][c4 * 4]) = v;
    }
#pragma unroll
    for (int l = 0; l < 20; l++) {
        int q = t + l * 256;
        Ws[q / 40][q % 40] = W[q];
    }
    __syncthreads();

    const int r = t >> 3;
    const int cg = t & 7;
    float acc[5] = {0.f, 0.f, 0.f, 0.f, 0.f};
#pragma unroll 8
    for (int k = 0; k < 128; k++) {
        float h = Ht[r][k];
#pragma unroll
        for (int j = 0; j < 5; j++)
            acc[j] = fmaf(h, Ws[k][cg * 5 + j], acc[j]);
    }
    int grow = row0 + r;
    if (grow < M) {
#pragma unroll
        for (int j = 0; j < 5; j++)
            C[(size_t)grow * 40 + cg * 5 + j] = __float2half_rn(acc[j]);
    }
}

// ===========================================================================
// Gather SpMM (feat=128, fp16 in, fp32 accum, fp16 out) + bias + ReLU
// ===========================================================================
__device__ __forceinline__ void acc4h(float& ax, float& ay, float& az, float& aw,
                                      float w, uint2 r) {
    float2 a01 = __half22float2(*reinterpret_cast<__half2*>(&r.x));
    float2 a23 = __half22float2(*reinterpret_cast<__half2*>(&r.y));
    ax = fmaf(w, a01.x, ax); ay = fmaf(w, a01.y, ay);
    az = fmaf(w, a23.x, az); aw = fmaf(w, a23.y, aw);
}

__global__ void __launch_bounds__(256) spmm_csr128h(
    const __half* __restrict__ H, const int* __restrict__ rp,
    const uint32_t* __restrict__ pe, const float* __restrict__ bias,
    __half* __restrict__ out, int M) {
    int row = blockIdx.x * 8 + (threadIdx.x >> 5);
    int lane = threadIdx.x & 31;
    if (row >= M) return;
    int p  = __ldg(rp + row);
    int pend = __ldg(rp + row + 1);

    const char* Hb = reinterpret_cast<const char*>(H) + lane * 8;
    float ax = 0.f, ay = 0.f, az = 0.f, aw = 0.f;

    for (; p + 4 <= pend; p += 4) {
        uint32_t e0 = __ldg(pe + p + 0), e1 = __ldg(pe + p + 1);
        uint32_t e2 = __ldg(pe + p + 2), e3 = __ldg(pe + p + 3);
        int s0, s1, s2, s3;
        float w0, w1, w2, w3;
        unpack_edge(e0, s0, w0);
        unpack_edge(e1, s1, w1);
        unpack_edge(e2, s2, w2);
        unpack_edge(e3, s3, w3);
        uint2 r0 = *reinterpret_cast<const uint2*>(Hb + (size_t)s0 * 256);
        uint2 r1 = *reinterpret_cast<const uint2*>(Hb + (size_t)s1 * 256);
        uint2 r2 = *reinterpret_cast<const uint2*>(Hb + (size_t)s2 * 256);
        uint2 r3 = *reinterpret_cast<const uint2*>(Hb + (size_t)s3 * 256);
        acc4h(ax, ay, az, aw, w0, r0);
        acc4h(ax, ay, az, aw, w1, r1);
        acc4h(ax, ay, az, aw, w2, r2);
        acc4h(ax, ay, az, aw, w3, r3);
    }
    for (; p < pend; p++) {
        int s;
        float w;
        unpack_edge(__ldg(pe + p), s, w);
        uint2 r0 = *reinterpret_cast<const uint2*>(Hb + (size_t)s * 256);
        acc4h(ax, ay, az, aw, w, r0);
    }

    float4 b4 = *reinterpret_cast<const float4*>(bias + lane * 4);
    __half2 o01 = __floats2half2_rn(fmaxf(ax + b4.x, 0.f), fmaxf(ay + b4.y, 0.f));
    __half2 o23 = __floats2half2_rn(fmaxf(az + b4.z, 0.f), fmaxf(aw + b4.w, 0.f));
    uint2 st;
    st.x = *reinterpret_cast<uint32_t*>(&o01);
    st.y = *reinterpret_cast<uint32_t*>(&o23);
    *reinterpret_cast<uint2*>(reinterpret_cast<char*>(out) + (size_t)row * 256 + lane * 8) = st;
}

// ===========================================================================
// Gather SpMM (feat=40, fp16 logits, fp32 accum) + bias + log_softmax
// ===========================================================================
__global__ void __launch_bounds__(256) spmm_csr40_lsm(
    const __half* __restrict__ C, const int* __restrict__ rp,
    const uint32_t* __restrict__ pe, const float* __restrict__ b,
    float* __restrict__ out, int M) {
    int row = blockIdx.x * 8 + (threadIdx.x >> 5);
    int lane = threadIdx.x & 31;
    if (row >= M) return;
    int p  = __ldg(rp + row);
    int pend = __ldg(rp + row + 1);

    float a0 = 0.f, a1 = 0.f;
    for (; p + 2 <= pend; p += 2) {
        int s0, s1;
        float w0, w1;
        unpack_edge(__ldg(pe + p), s0, w0);
        unpack_edge(__ldg(pe + p + 1), s1, w1);
        const __half* c0 = C + (size_t)s0 * 40;
        const __half* c1 = C + (size_t)s1 * 40;
        float x0 = __half2float(__ldg(c0 + lane));
        float x1 = __half2float(__ldg(c1 + lane));
        float y0 = (lane < 8) ? __half2float(__ldg(c0 + 32 + lane)) : 0.f;
        float y1 = (lane < 8) ? __half2float(__ldg(c1 + 32 + lane)) : 0.f;
        a0 = fmaf(w0, x0, a0); a0 = fmaf(w1, x1, a0);
        a1 = fmaf(w0, y0, a1); a1 = fmaf(w1, y1, a1);
    }
    if (p < pend) {
        int s;
        float w;
        unpack_edge(__ldg(pe + p), s, w);
        const __half* c0 = C + (size_t)s * 40;
        a0 = fmaf(w, __half2float(__ldg(c0 + lane)), a0);
        if (lane < 8) a1 = fmaf(w, __half2float(__ldg(c0 + 32 + lane)), a1);
    }

    float v0 = a0 + __ldg(b + lane);
    float v1 = (lane < 8) ? (a1 + __ldg(b + 32 + lane)) : -INFINITY;

    float m = fmaxf(v0, v1);
#pragma unroll
    for (int o = 16; o > 0; o >>= 1) m = fmaxf(m, __shfl_xor_sync(0xffffffffu, m, o));
    float s = __expf(v0 - m) + ((lane < 8) ? __expf(v1 - m) : 0.f);
#pragma unroll
    for (int o = 16; o > 0; o >>= 1) s += __shfl_xor_sync(0xffffffffu, s, o);
    float ls = m + __logf(s);

    out[(size_t)row * 40 + lane] = v0 - ls;
    if (lane < 8) out[(size_t)row * 40 + 32 + lane] = v1 - ls;
}

// ===========================================================================
extern "C" void kernel_launch(void* const* d_in, const int* in_sizes, int n_in,
                              void* d_out, int out_size) {
    const float* x    = (const float*)d_in[0];
    const int*   esrc = (const int*)  d_in[1];
    const int*   edst = (const int*)  d_in[2];
    const float* ew   = (const float*)d_in[3];
    const float* W1   = (const float*)d_in[4];
    const float* b1   = (const float*)d_in[5];
    const float* Wh   = (const float*)d_in[6];
    const float* bh   = (const float*)d_in[7];
    const float* W2   = (const float*)d_in[8];
    const float* b2   = (const float*)d_in[9];
    float* out = (float*)d_out;

    const int M  = in_sizes[0] / NFEAT;   // 50000
    const int nE = in_sizes[1];           // 1600000

    __half *Ah, *Bh, *Ch;
    int *cnt, *cursor, *rp, *aggs, *ctr;
    uint32_t *pe, *stage;
    uint32_t *W1h, *W1l, *Whh, *Whl;
    cudaGetSymbolAddress((void**)&Ah, g_Ah);
    cudaGetSymbolAddress((void**)&Bh, g_Bh);
    cudaGetSymbolAddress((void**)&Ch, g_Ch);
    cudaGetSymbolAddress((void**)&cnt, g_cnt);
    cudaGetSymbolAddress((void**)&cursor, g_cursor);
    cudaGetSymbolAddress((void**)&rp, g_rp);
    cudaGetSymbolAddress((void**)&aggs, g_aggs);
    cudaGetSymbolAddress((void**)&ctr, g_scanctr);
    cudaGetSymbolAddress((void**)&pe, g_pe);
    cudaGetSymbolAddress((void**)&stage, g_stage);
    cudaGetSymbolAddress((void**)&W1h, g_W1h);
    cudaGetSymbolAddress((void**)&W1l, g_W1l);
    cudaGetSymbolAddress((void**)&Whh, g_Whh);
    cudaGetSymbolAddress((void**)&Whl, g_Whl);

    static cudaStream_t s2 = nullptr;
    static cudaEvent_t evF = nullptr, evJ = nullptr;
    if (!s2) {
        cudaStreamCreateWithFlags(&s2, cudaStreamNonBlocking);
        cudaEventCreateWithFlags(&evF, cudaEventDisableTiming);
        cudaEventCreateWithFlags(&evJ, cudaEventDisableTiming);
        cudaFuncSetAttribute(mma_gemm128<float>,
                             cudaFuncAttributeMaxDynamicSharedMemorySize, SM_U32 * 4);
        cudaFuncSetAttribute(mma_gemm128<__half>,
                             cudaFuncAttributeMaxDynamicSharedMemorySize, SM_U32 * 4);
    }

    const int nb = (M + 255) / 256;           // 196
    const int gemmBlocks = (M + 127) / 128;   // 391
    const int spmmBlocks = (M + 7) / 8;
    const int nE4 = nE / 4;

    // ---- Fork: CSR build on s2, weight pack + layer-1 GEMM on main ----
    cudaEventRecord(evF, 0);
    cudaStreamWaitEvent(s2, evF, 0);

    zero_int4<<<(M / 4 + 255) / 256, 256, 0, s2>>>((int4*)cnt, (M + 3) / 4, ctr);
    hist_stage<<<(nE4 + 255) / 256, 256, 0, s2>>>(
        (const int4*)esrc, (const int4*)edst, (const float4*)ew, cnt, (uint4*)stage, nE4);
    scan_lookback<<<nb, 256, 0, s2>>>(cnt, rp, cursor, ctr, aggs, M, nb, nE);
    scatter_staged<<<(nE4 + 1 + 255) / 256, 256, 0, s2>>>(
        (const uint4*)stage, (const int4*)edst, cursor, pe, nE4, esrc, edst, ew, nE);
    cudaEventRecord(evJ, s2);

    conv_weights<<<160, 256>>>(W1, Wh, W1h, W1l, Whh, Whl);
    mma_gemm128<float><<<gemmBlocks, 256, SM_U32 * 4>>>(x, W1h, W1l, Ah, M, NFEAT);

    cudaStreamWaitEvent(0, evJ, 0);   // join

    // Layer 1 aggregation (fp16 out)
    spmm_csr128h<<<spmmBlocks, 256>>>(Ah, rp, pe, b1, Bh, M);

    // Layer 2 (fp16 in)
    mma_gemm128<__half><<<gemmBlocks, 256, SM_U32 * 4>>>(Bh, Whh, Whl, Ah, M, NHID);
    spmm_csr128h<<<spmmBlocks, 256>>>(Ah, rp, pe, bh, Bh, M);

    // Layer 3 + log_softmax
    sgemm40<<<(M + 31) / 32, 256>>>(Bh, W2, Ch, M);
    spmm_csr40_lsm<<<spmmBlocks, 256>>>(Ch, rp, pe, b2, out, M);
}

// round 17
// speedup vs baseline: 1.0539x; 1.0207x over previous
#include <cuda_runtime.h>
#include <cuda_bf16.h>
#include <cuda_fp16.h>
#include <math.h>
#include <cstdint>

// ---------------------------------------------------------------------------
// GCN: 3x { H = A_sparse @ (H @ W) + b (,ReLU) } -> log_softmax
// N=50000, E=1.6M, 512 -> 128 -> 128 -> 40
// Round 17: R16 base (best: 269.8) + GEMM2 native-fp16 path: A-stage is pure
//           copies (input already fp16), W pre-packed as fp16 hi/lo, 2 MMAs
//           per k-step instead of 3.
// ---------------------------------------------------------------------------

#define NNODES 50000
#define NEDGES 1600000
#define NFEAT 512
#define NHID  128
#define NCLASS 40

// Scratch (__device__ globals; no allocations allowed)
__device__ __half g_Ah[NNODES * NHID];
__device__ __half g_Bh[NNODES * NHID];
__device__ __half g_Ch[NNODES * NCLASS];
__device__ int    g_cnt[NNODES];
__device__ int    g_cursor[NNODES];
__device__ int    g_rp[NNODES + 1];
__device__ int    g_aggs[256];
__device__ int    g_scanctr;
__device__ uint32_t g_stage[NEDGES];     // packed records in original edge order
__device__ uint32_t g_pe[NEDGES];        // packed records in CSR order
__device__ uint32_t g_W1h[256 * 128];    // bf16 hi plane (GEMM1)
__device__ uint32_t g_W1l[256 * 128];    // bf16 lo plane (GEMM1)
__device__ uint32_t g_Whh[64 * 128];     // fp16 hi plane (GEMM2)
__device__ uint32_t g_Whl[64 * 128];     // fp16 lo plane (GEMM2)

// ===========================================================================
// helpers
// ===========================================================================
// Packed bf16 hi/lo split via cvt.rn.bf16x2.f32 (hi = pack(x,y); lo = residuals)
__device__ __forceinline__ void cvt_hilo(float x, float y, uint32_t& hi, uint32_t& lo) {
    uint32_t h;
    asm("cvt.rn.bf16x2.f32 %0, %1, %2;" : "=r"(h) : "f"(y), "f"(x));
    float hx = __uint_as_float(h << 16);
    float hy = __uint_as_float(h & 0xFFFF0000u);
    float rx = x - hx;
    float ry = y - hy;
    uint32_t l;
    asm("cvt.rn.bf16x2.f32 %0, %1, %2;" : "=r"(l) : "f"(ry), "f"(rx));
    hi = h; lo = l;
}

// fp16 hi/lo split (for GEMM2 weights): hi = half2(x,y), lo = residual half2
__device__ __forceinline__ void cvt_hilo_f16(float x, float y, uint32_t& hi, uint32_t& lo) {
    __half hx = __float2half_rn(x);
    __half hy = __float2half_rn(y);
    float rx = x - __half2float(hx);
    float ry = y - __half2float(hy);
    __half2 H; H.x = hx; H.y = hy;
    __half2 L = __floats2half2_rn(rx, ry);
    hi = *reinterpret_cast<uint32_t*>(&H);
    lo = *reinterpret_cast<uint32_t*>(&L);
}

__device__ __forceinline__ void mma16816(float* d, const uint32_t* a, uint32_t b0, uint32_t b1) {
    asm volatile(
        "mma.sync.aligned.m16n8k16.row.col.f32.bf16.bf16.f32 "
        "{%0,%1,%2,%3}, {%4,%5,%6,%7}, {%8,%9}, {%0,%1,%2,%3};"
        : "+f"(d[0]), "+f"(d[1]), "+f"(d[2]), "+f"(d[3])
        : "r"(a[0]), "r"(a[1]), "r"(a[2]), "r"(a[3]), "r"(b0), "r"(b1));
}

__device__ __forceinline__ void mma16816h(float* d, const uint32_t* a, uint32_t b0, uint32_t b1) {
    asm volatile(
        "mma.sync.aligned.m16n8k16.row.col.f32.f16.f16.f32 "
        "{%0,%1,%2,%3}, {%4,%5,%6,%7}, {%8,%9}, {%0,%1,%2,%3};"
        : "+f"(d[0]), "+f"(d[1]), "+f"(d[2]), "+f"(d[3])
        : "r"(a[0]), "r"(a[1]), "r"(a[2]), "r"(a[3]), "r"(b0), "r"(b1));
}

__device__ __forceinline__ float4 load4f(const float* p) {
    return *reinterpret_cast<const float4*>(p);
}

__device__ __forceinline__ void unpack_edge(uint32_t rec, int& s, float& w) {
    s = (int)(rec & 0xFFFFu);
    w = __half2float(__ushort_as_half((unsigned short)(rec >> 16)));
}

__device__ __forceinline__ uint32_t pack_edge(int s, float w) {
    return (uint32_t)s | ((uint32_t)__half_as_ushort(__float2half_rn(w)) << 16);
}

// SMEM layout (u32 units). A tiles: [m=128][k2=32 + pad4]. B: [k2=32][n=128+8].
#define AH_OFF 0
#define AL_OFF 4608
#define BH_OFF 9216
#define BL_OFF 13568
#define SM_U32 17920   // 71680 bytes

// ===========================================================================
// Weight pre-pack: W1 -> bf16 hi/lo; Wh -> fp16 hi/lo
// ===========================================================================
__global__ void conv_weights(const float* __restrict__ W1, const float* __restrict__ Wh,
                             uint32_t* __restrict__ W1h, uint32_t* __restrict__ W1l,
                             uint32_t* __restrict__ Whh, uint32_t* __restrict__ Whl) {
    int i = blockIdx.x * 256 + threadIdx.x;
    if (i < 256 * 128) {
        int k2 = i >> 7, n = i & 127;
        float v0 = __ldg(W1 + (size_t)(2 * k2) * 128 + n);
        float v1 = __ldg(W1 + (size_t)(2 * k2 + 1) * 128 + n);
        uint32_t h, lo;
        cvt_hilo(v0, v1, h, lo);
        W1h[i] = h; W1l[i] = lo;
    } else if (i < 256 * 128 + 64 * 128) {
        int j = i - 256 * 128;
        int k2 = j >> 7, n = j & 127;
        float v0 = __ldg(Wh + (size_t)(2 * k2) * 128 + n);
        float v1 = __ldg(Wh + (size_t)(2 * k2 + 1) * 128 + n);
        uint32_t h, lo;
        cvt_hilo_f16(v0, v1, h, lo);
        Whh[j] = h; Whl[j] = lo;
    }
}

// ===========================================================================
// GEMM1: C[M,128] = A[M,K] @ W (bf16 hi/lo pre-packed); A fp32; fp16 out.
// ===========================================================================
__global__ void __launch_bounds__(256, 2) mma_gemm128(
    const float* __restrict__ A,
    const uint32_t* __restrict__ Wph, const uint32_t* __restrict__ Wpl,
    __half* __restrict__ C, int M, int K) {
    extern __shared__ uint32_t sm[];
    uint32_t* AH = sm + AH_OFF;
    uint32_t* AL = sm + AL_OFF;
    uint32_t* BH = sm + BH_OFF;
    uint32_t* BL = sm + BL_OFF;

    const int t = threadIdx.x;
    const int lane = t & 31;
    const int wid = t >> 5;
    const int warpM = wid >> 1;
    const int warpN = wid & 1;
    const int row0 = blockIdx.x * 128;

    float acc[2][8][4];
#pragma unroll
    for (int mt = 0; mt < 2; mt++)
#pragma unroll
        for (int nt = 0; nt < 8; nt++)
#pragma unroll
            for (int e = 0; e < 4; e++) acc[mt][nt][e] = 0.f;

    const int r4 = lane >> 2;
    const int q4 = lane & 3;

    const int nChunks = K >> 6;
    for (int c = 0; c < nChunks; c++) {
        const int k0 = c << 6;
        const int k0h = c << 5;
        __syncthreads();

#pragma unroll
        for (int l = 0; l < 8; l++) {
            int q = t + l * 256;
            int m = q >> 4;
            int c4 = q & 15;
            float4 v = make_float4(0.f, 0.f, 0.f, 0.f);
            if (row0 + m < M)
                v = load4f(A + (size_t)(row0 + m) * K + k0 + c4 * 4);
            uint32_t h0, l0, h1, l1;
            cvt_hilo(v.x, v.y, h0, l0);
            cvt_hilo(v.z, v.w, h1, l1);
            int base = m * 36 + c4 * 2;
            AH[base] = h0; AH[base + 1] = h1;
            AL[base] = l0; AL[base + 1] = l1;
        }
#pragma unroll
        for (int l = 0; l < 4; l++) {
            int q = t + l * 256;
            int k2 = q >> 5;
            int n4 = q & 31;
            size_t goff = (size_t)(k0h + k2) * 128 + n4 * 4;
            uint4 vh = __ldg(reinterpret_cast<const uint4*>(Wph + goff));
            uint4 vl = __ldg(reinterpret_cast<const uint4*>(Wpl + goff));
            *reinterpret_cast<uint4*>(&BH[k2 * 136 + n4 * 4]) = vh;
            *reinterpret_cast<uint4*>(&BL[k2 * 136 + n4 * 4]) = vl;
        }
        __syncthreads();

#pragma unroll
        for (int k8 = 0; k8 < 4; k8++) {
            int klo = k8 * 8 + q4;
            uint32_t ah[2][4], al[2][4];
#pragma unroll
            for (int mt = 0; mt < 2; mt++) {
                int base = (warpM * 32 + mt * 16 + r4) * 36;
                ah[mt][0] = AH[base + klo];
                ah[mt][1] = AH[base + 8 * 36 + klo];
                ah[mt][2] = AH[base + klo + 4];
                ah[mt][3] = AH[base + 8 * 36 + klo + 4];
                al[mt][0] = AL[base + klo];
                al[mt][1] = AL[base + 8 * 36 + klo];
                al[mt][2] = AL[base + klo + 4];
                al[mt][3] = AL[base + 8 * 36 + klo + 4];
            }
#pragma unroll
            for (int nt = 0; nt < 8; nt++) {
                int nB = warpN * 64 + nt * 8 + r4;
                uint32_t bh0 = BH[klo * 136 + nB];
                uint32_t bh1 = BH[(klo + 4) * 136 + nB];
                uint32_t bl0 = BL[klo * 136 + nB];
                uint32_t bl1 = BL[(klo + 4) * 136 + nB];
#pragma unroll
                for (int mt = 0; mt < 2; mt++) {
                    mma16816(acc[mt][nt], ah[mt], bh0, bh1);
                    mma16816(acc[mt][nt], ah[mt], bl0, bl1);
                    mma16816(acc[mt][nt], al[mt], bh0, bh1);
                }
            }
        }
    }

#pragma unroll
    for (int mt = 0; mt < 2; mt++) {
        int rowA = row0 + warpM * 32 + mt * 16 + r4;
        int rowB = rowA + 8;
#pragma unroll
        for (int nt = 0; nt < 8; nt++) {
            int col = warpN * 64 + nt * 8 + q4 * 2;
            if (rowA < M)
                *reinterpret_cast<__half2*>(C + (size_t)rowA * 128 + col) =
                    __floats2half2_rn(acc[mt][nt][0], acc[mt][nt][1]);
            if (rowB < M)
                *reinterpret_cast<__half2*>(C + (size_t)rowB * 128 + col) =
                    __floats2half2_rn(acc[mt][nt][2], acc[mt][nt][3]);
        }
    }
}

// ===========================================================================
// GEMM2: C[M,128] = A[M,128] @ W; A fp16 (exact), W fp16 hi/lo; 2 MMAs/step.
// A-stage = pure uint2 copies. No AL plane.
// ===========================================================================
__global__ void __launch_bounds__(256, 2) mma_gemm128_f16(
    const __half* __restrict__ A,
    const uint32_t* __restrict__ Wph, const uint32_t* __restrict__ Wpl,
    __half* __restrict__ C, int M) {
    extern __shared__ uint32_t sm[];
    uint32_t* AH = sm + AH_OFF;
    uint32_t* BH = sm + BH_OFF;
    uint32_t* BL = sm + BL_OFF;

    const int t = threadIdx.x;
    const int lane = t & 31;
    const int wid = t >> 5;
    const int warpM = wid >> 1;
    const int warpN = wid & 1;
    const int row0 = blockIdx.x * 128;

    float acc[2][8][4];
#pragma unroll
    for (int mt = 0; mt < 2; mt++)
#pragma unroll
        for (int nt = 0; nt < 8; nt++)
#pragma unroll
            for (int e = 0; e < 4; e++) acc[mt][nt][e] = 0.f;

    const int r4 = lane >> 2;
    const int q4 = lane & 3;

#pragma unroll
    for (int c = 0; c < 2; c++) {
        const int k0 = c << 6;
        const int k0h = c << 5;
        __syncthreads();

        // A-stage: copy fp16 pairs straight into AH (no conversion)
#pragma unroll
        for (int l = 0; l < 8; l++) {
            int q = t + l * 256;
            int m = q >> 4;
            int c4 = q & 15;
            uint2 u = make_uint2(0u, 0u);
            if (row0 + m < M)
                u = *reinterpret_cast<const uint2*>(A + (size_t)(row0 + m) * 128 + k0 + c4 * 4);
            int base = m * 36 + c4 * 2;
            AH[base] = u.x; AH[base + 1] = u.y;
        }
#pragma unroll
        for (int l = 0; l < 4; l++) {
            int q = t + l * 256;
            int k2 = q >> 5;
            int n4 = q & 31;
            size_t goff = (size_t)(k0h + k2) * 128 + n4 * 4;
            uint4 vh = __ldg(reinterpret_cast<const uint4*>(Wph + goff));
            uint4 vl = __ldg(reinterpret_cast<const uint4*>(Wpl + goff));
            *reinterpret_cast<uint4*>(&BH[k2 * 136 + n4 * 4]) = vh;
            *reinterpret_cast<uint4*>(&BL[k2 * 136 + n4 * 4]) = vl;
        }
        __syncthreads();

#pragma unroll
        for (int k8 = 0; k8 < 4; k8++) {
            int klo = k8 * 8 + q4;
            uint32_t ah[2][4];
#pragma unroll
            for (int mt = 0; mt < 2; mt++) {
                int base = (warpM * 32 + mt * 16 + r4) * 36;
                ah[mt][0] = AH[base + klo];
                ah[mt][1] = AH[base + 8 * 36 + klo];
                ah[mt][2] = AH[base + klo + 4];
                ah[mt][3] = AH[base + 8 * 36 + klo + 4];
            }
#pragma unroll
            for (int nt = 0; nt < 8; nt++) {
                int nB = warpN * 64 + nt * 8 + r4;
                uint32_t bh0 = BH[klo * 136 + nB];
                uint32_t bh1 = BH[(klo + 4) * 136 + nB];
                uint32_t bl0 = BL[klo * 136 + nB];
                uint32_t bl1 = BL[(klo + 4) * 136 + nB];
#pragma unroll
                for (int mt = 0; mt < 2; mt++) {
                    mma16816h(acc[mt][nt], ah[mt], bh0, bh1);
                    mma16816h(acc[mt][nt], ah[mt], bl0, bl1);
                }
            }
        }
    }

#pragma unroll
    for (int mt = 0; mt < 2; mt++) {
        int rowA = row0 + warpM * 32 + mt * 16 + r4;
        int rowB = rowA + 8;
#pragma unroll
        for (int nt = 0; nt < 8; nt++) {
            int col = warpN * 64 + nt * 8 + q4 * 2;
            if (rowA < M)
                *reinterpret_cast<__half2*>(C + (size_t)rowA * 128 + col) =
                    __floats2half2_rn(acc[mt][nt][0], acc[mt][nt][1]);
            if (rowB < M)
                *reinterpret_cast<__half2*>(C + (size_t)rowB * 128 + col) =
                    __floats2half2_rn(acc[mt][nt][2], acc[mt][nt][3]);
        }
    }
}

// ===========================================================================
// CSR build: zero(+ctr) -> hist+stage -> lookback scan -> scatter
// ===========================================================================
__global__ void zero_int4(int4* p, int n4, int* ctr) {
    int i = blockIdx.x * blockDim.x + threadIdx.x;
    if (i < n4) p[i] = make_int4(0, 0, 0, 0);
    if (i == 0) *ctr = 0;
}

__global__ void hist_stage(const int4* __restrict__ src4, const int4* __restrict__ dst4,
                           const float4* __restrict__ w4, int* __restrict__ cnt,
                           uint4* __restrict__ stage, int n4) {
    int e = blockIdx.x * blockDim.x + threadIdx.x;
    if (e >= n4) return;
    int4 s = __ldg(src4 + e);
    int4 d = __ldg(dst4 + e);
    float4 ww = __ldg(w4 + e);
    uint4 r;
    r.x = pack_edge(s.x, ww.x);
    r.y = pack_edge(s.y, ww.y);
    r.z = pack_edge(s.z, ww.z);
    r.w = pack_edge(s.w, ww.w);
    stage[e] = r;
    atomicAdd(&cnt[d.x], 1);
    atomicAdd(&cnt[d.y], 1);
    atomicAdd(&cnt[d.z], 1);
    atomicAdd(&cnt[d.w], 1);
}

__global__ void scan_lookback(const int* __restrict__ cnt, int* __restrict__ rp,
                              int* __restrict__ cursor, int* __restrict__ ctr,
                              int* __restrict__ aggs, int n, int nb, int nE) {
    __shared__ int wsum[8];
    __shared__ int red[8];
    const int lane = threadIdx.x & 31;
    const int wid  = threadIdx.x >> 5;
    int i = blockIdx.x * 256 + threadIdx.x;
    int v = (i < n) ? cnt[i] : 0;

    int incl = v;
#pragma unroll
    for (int o = 1; o < 32; o <<= 1) {
        int tt = __shfl_up_sync(0xffffffffu, incl, o);
        if (lane >= o) incl += tt;
    }
    if (lane == 31) wsum[wid] = incl;
    __syncthreads();
    if (wid == 0) {
        int s = (lane < 8) ? wsum[lane] : 0;
#pragma unroll
        for (int o = 1; o < 8; o <<= 1) {
            int tt = __shfl_up_sync(0xffffffffu, s, o);
            if (lane >= o) s += tt;
        }
        if (lane < 8) wsum[lane] = s;
    }
    __syncthreads();
    int excl = (wid ? wsum[wid - 1] : 0) + incl - v;
    int total = wsum[7];

    if (threadIdx.x == 0) {
        aggs[blockIdx.x] = total;
        __threadfence();
        atomicAdd(ctr, 1);
        while (atomicAdd(ctr, 0) < nb) { }
    }
    __syncthreads();
    __threadfence();

    int a = (threadIdx.x < nb && threadIdx.x < blockIdx.x) ? aggs[threadIdx.x] : 0;
#pragma unroll
    for (int o = 16; o > 0; o >>= 1) a += __shfl_xor_sync(0xffffffffu, a, o);
    if (lane == 0) red[wid] = a;
    __syncthreads();
    if (threadIdx.x == 0) {
        int s = 0;
#pragma unroll
        for (int j = 0; j < 8; j++) s += red[j];
        red[0] = s;
    }
    __syncthreads();
    int off = red[0];
    if (i < n) {
        int val = excl + off;
        rp[i] = val;
        cursor[i] = val;
    }
    if (blockIdx.x == 0 && threadIdx.x == 0) rp[n] = nE;
}

__global__ void scatter_staged(const uint4* __restrict__ stage, const int4* __restrict__ dst4,
                               int* __restrict__ cursor, uint32_t* __restrict__ pe,
                               int n4,
                               const int* __restrict__ src, const int* __restrict__ dst,
                               const float* __restrict__ w, int nE) {
    int e = blockIdx.x * blockDim.x + threadIdx.x;
    if (e < n4) {
        uint4 r = __ldg(stage + e);
        int4 d = __ldg(dst4 + e);
        int p0 = atomicAdd(&cursor[d.x], 1);
        pe[p0] = r.x;
        int p1 = atomicAdd(&cursor[d.y], 1);
        pe[p1] = r.y;
        int p2 = atomicAdd(&cursor[d.z], 1);
        pe[p2] = r.z;
        int p3 = atomicAdd(&cursor[d.w], 1);
        pe[p3] = r.w;
    } else if (e == n4) {
        for (int k = n4 * 4; k < nE; k++) {
            int dd = __ldg(dst + k);
            int pos = atomicAdd(&cursor[dd], 1);
            pe[pos] = pack_edge(__ldg(src + k), __ldg(w + k));
        }
    }
}

// ===========================================================================
// GEMM3: C[M,40] = H[M,128] @ W2[128,40]; fp16 in, fp16 out; fp32 math.
// ===========================================================================
__device__ __forceinline__ float4 load4h(const __half* p) {
    uint2 u = *reinterpret_cast<const uint2*>(p);
    float2 a = __half22float2(*reinterpret_cast<__half2*>(&u.x));
    float2 b = __half22float2(*reinterpret_cast<__half2*>(&u.y));
    return make_float4(a.x, a.y, b.x, b.y);
}

__global__ void sgemm40(const __half* __restrict__ H, const float* __restrict__ W,
                        __half* __restrict__ C, int M) {
    __shared__ float Ht[32][132];
    __shared__ float Ws[128][40];

    const int t = threadIdx.x;
    const int row0 = blockIdx.x * 32;

#pragma unroll
    for (int l = 0; l < 4; l++) {
        int q = t + l * 256;
        int r = q >> 5;
        int c4 = q & 31;
        float4 v = make_float4(0.f, 0.f, 0.f, 0.f);
        if (row0 + r < M)
            v = load4h(H + (size_t)(row0 + r) * 128 + c4 * 4);
        *reinterpret_cast<float4*>(&Ht[r][c4 * 4]) = v;
    }
#pragma unroll
    for (int l = 0; l < 20; l++) {
        int q = t + l * 256;
        Ws[q / 40][q % 40] = W[q];
    }
    __syncthreads();

    const int r = t >> 3;
    const int cg = t & 7;
    float acc[5] = {0.f, 0.f, 0.f, 0.f, 0.f};
#pragma unroll 8
    for (int k = 0; k < 128; k++) {
        float h = Ht[r][k];
#pragma unroll
        for (int j = 0; j < 5; j++)
            acc[j] = fmaf(h, Ws[k][cg * 5 + j], acc[j]);
    }
    int grow = row0 + r;
    if (grow < M) {
#pragma unroll
        for (int j = 0; j < 5; j++)
            C[(size_t)grow * 40 + cg * 5 + j] = __float2half_rn(acc[j]);
    }
}

// ===========================================================================
// Gather SpMM (feat=128, fp16 in, fp32 accum, fp16 out) + bias + ReLU
// ===========================================================================
__device__ __forceinline__ void acc4h(float& ax, float& ay, float& az, float& aw,
                                      float w, uint2 r) {
    float2 a01 = __half22float2(*reinterpret_cast<__half2*>(&r.x));
    float2 a23 = __half22float2(*reinterpret_cast<__half2*>(&r.y));
    ax = fmaf(w, a01.x, ax); ay = fmaf(w, a01.y, ay);
    az = fmaf(w, a23.x, az); aw = fmaf(w, a23.y, aw);
}

__global__ void __launch_bounds__(256) spmm_csr128h(
    const __half* __restrict__ H, const int* __restrict__ rp,
    const uint32_t* __restrict__ pe, const float* __restrict__ bias,
    __half* __restrict__ out, int M) {
    int row = blockIdx.x * 8 + (threadIdx.x >> 5);
    int lane = threadIdx.x & 31;
    if (row >= M) return;
    int p  = __ldg(rp + row);
    int pend = __ldg(rp + row + 1);

    const char* Hb = reinterpret_cast<const char*>(H) + lane * 8;
    float ax = 0.f, ay = 0.f, az = 0.f, aw = 0.f;

    for (; p + 4 <= pend; p += 4) {
        uint32_t e0 = __ldg(pe + p + 0), e1 = __ldg(pe + p + 1);
        uint32_t e2 = __ldg(pe + p + 2), e3 = __ldg(pe + p + 3);
        int s0, s1, s2, s3;
        float w0, w1, w2, w3;
        unpack_edge(e0, s0, w0);
        unpack_edge(e1, s1, w1);
        unpack_edge(e2, s2, w2);
        unpack_edge(e3, s3, w3);
        uint2 r0 = *reinterpret_cast<const uint2*>(Hb + (size_t)s0 * 256);
        uint2 r1 = *reinterpret_cast<const uint2*>(Hb + (size_t)s1 * 256);
        uint2 r2 = *reinterpret_cast<const uint2*>(Hb + (size_t)s2 * 256);
        uint2 r3 = *reinterpret_cast<const uint2*>(Hb + (size_t)s3 * 256);
        acc4h(ax, ay, az, aw, w0, r0);
        acc4h(ax, ay, az, aw, w1, r1);
        acc4h(ax, ay, az, aw, w2, r2);
        acc4h(ax, ay, az, aw, w3, r3);
    }
    for (; p < pend; p++) {
        int s;
        float w;
        unpack_edge(__ldg(pe + p), s, w);
        uint2 r0 = *reinterpret_cast<const uint2*>(Hb + (size_t)s * 256);
        acc4h(ax, ay, az, aw, w, r0);
    }

    float4 b4 = *reinterpret_cast<const float4*>(bias + lane * 4);
    __half2 o01 = __floats2half2_rn(fmaxf(ax + b4.x, 0.f), fmaxf(ay + b4.y, 0.f));
    __half2 o23 = __floats2half2_rn(fmaxf(az + b4.z, 0.f), fmaxf(aw + b4.w, 0.f));
    uint2 st;
    st.x = *reinterpret_cast<uint32_t*>(&o01);
    st.y = *reinterpret_cast<uint32_t*>(&o23);
    *reinterpret_cast<uint2*>(reinterpret_cast<char*>(out) + (size_t)row * 256 + lane * 8) = st;
}

// ===========================================================================
// Gather SpMM (feat=40, fp16 logits, fp32 accum) + bias + log_softmax
// ===========================================================================
__global__ void __launch_bounds__(256) spmm_csr40_lsm(
    const __half* __restrict__ C, const int* __restrict__ rp,
    const uint32_t* __restrict__ pe, const float* __restrict__ b,
    float* __restrict__ out, int M) {
    int row = blockIdx.x * 8 + (threadIdx.x >> 5);
    int lane = threadIdx.x & 31;
    if (row >= M) return;
    int p  = __ldg(rp + row);
    int pend = __ldg(rp + row + 1);

    float a0 = 0.f, a1 = 0.f;
    for (; p + 2 <= pend; p += 2) {
        int s0, s1;
        float w0, w1;
        unpack_edge(__ldg(pe + p), s0, w0);
        unpack_edge(__ldg(pe + p + 1), s1, w1);
        const __half* c0 = C + (size_t)s0 * 40;
        const __half* c1 = C + (size_t)s1 * 40;
        float x0 = __half2float(__ldg(c0 + lane));
        float x1 = __half2float(__ldg(c1 + lane));
        float y0 = (lane < 8) ? __half2float(__ldg(c0 + 32 + lane)) : 0.f;
        float y1 = (lane < 8) ? __half2float(__ldg(c1 + 32 + lane)) : 0.f;
        a0 = fmaf(w0, x0, a0); a0 = fmaf(w1, x1, a0);
        a1 = fmaf(w0, y0, a1); a1 = fmaf(w1, y1, a1);
    }
    if (p < pend) {
        int s;
        float w;
        unpack_edge(__ldg(pe + p), s, w);
        const __half* c0 = C + (size_t)s * 40;
        a0 = fmaf(w, __half2float(__ldg(c0 + lane)), a0);
        if (lane < 8) a1 = fmaf(w, __half2float(__ldg(c0 + 32 + lane)), a1);
    }

    float v0 = a0 + __ldg(b + lane);
    float v1 = (lane < 8) ? (a1 + __ldg(b + 32 + lane)) : -INFINITY;

    float m = fmaxf(v0, v1);
#pragma unroll
    for (int o = 16; o > 0; o >>= 1) m = fmaxf(m, __shfl_xor_sync(0xffffffffu, m, o));
    float s = __expf(v0 - m) + ((lane < 8) ? __expf(v1 - m) : 0.f);
#pragma unroll
    for (int o = 16; o > 0; o >>= 1) s += __shfl_xor_sync(0xffffffffu, s, o);
    float ls = m + __logf(s);

    out[(size_t)row * 40 + lane] = v0 - ls;
    if (lane < 8) out[(size_t)row * 40 + 32 + lane] = v1 - ls;
}

// ===========================================================================
extern "C" void kernel_launch(void* const* d_in, const int* in_sizes, int n_in,
                              void* d_out, int out_size) {
    const float* x    = (const float*)d_in[0];
    const int*   esrc = (const int*)  d_in[1];
    const int*   edst = (const int*)  d_in[2];
    const float* ew   = (const float*)d_in[3];
    const float* W1   = (const float*)d_in[4];
    const float* b1   = (const float*)d_in[5];
    const float* Wh   = (const float*)d_in[6];
    const float* bh   = (const float*)d_in[7];
    const float* W2   = (const float*)d_in[8];
    const float* b2   = (const float*)d_in[9];
    float* out = (float*)d_out;

    const int M  = in_sizes[0] / NFEAT;   // 50000
    const int nE = in_sizes[1];           // 1600000

    __half *Ah, *Bh, *Ch;
    int *cnt, *cursor, *rp, *aggs, *ctr;
    uint32_t *pe, *stage;
    uint32_t *W1h, *W1l, *Whh, *Whl;
    cudaGetSymbolAddress((void**)&Ah, g_Ah);
    cudaGetSymbolAddress((void**)&Bh, g_Bh);
    cudaGetSymbolAddress((void**)&Ch, g_Ch);
    cudaGetSymbolAddress((void**)&cnt, g_cnt);
    cudaGetSymbolAddress((void**)&cursor, g_cursor);
    cudaGetSymbolAddress((void**)&rp, g_rp);
    cudaGetSymbolAddress((void**)&aggs, g_aggs);
    cudaGetSymbolAddress((void**)&ctr, g_scanctr);
    cudaGetSymbolAddress((void**)&pe, g_pe);
    cudaGetSymbolAddress((void**)&stage, g_stage);
    cudaGetSymbolAddress((void**)&W1h, g_W1h);
    cudaGetSymbolAddress((void**)&W1l, g_W1l);
    cudaGetSymbolAddress((void**)&Whh, g_Whh);
    cudaGetSymbolAddress((void**)&Whl, g_Whl);

    static cudaStream_t s2 = nullptr;
    static cudaEvent_t evF = nullptr, evJ = nullptr;
    if (!s2) {
        cudaStreamCreateWithFlags(&s2, cudaStreamNonBlocking);
        cudaEventCreateWithFlags(&evF, cudaEventDisableTiming);
        cudaEventCreateWithFlags(&evJ, cudaEventDisableTiming);
        cudaFuncSetAttribute(mma_gemm128,
                             cudaFuncAttributeMaxDynamicSharedMemorySize, SM_U32 * 4);
        cudaFuncSetAttribute(mma_gemm128_f16,
                             cudaFuncAttributeMaxDynamicSharedMemorySize, SM_U32 * 4);
    }

    const int nb = (M + 255) / 256;           // 196
    const int gemmBlocks = (M + 127) / 128;   // 391
    const int spmmBlocks = (M + 7) / 8;
    const int nE4 = nE / 4;

    // ---- Fork: CSR build on s2, weight pack + layer-1 GEMM on main ----
    cudaEventRecord(evF, 0);
    cudaStreamWaitEvent(s2, evF, 0);

    zero_int4<<<(M / 4 + 255) / 256, 256, 0, s2>>>((int4*)cnt, (M + 3) / 4, ctr);
    hist_stage<<<(nE4 + 255) / 256, 256, 0, s2>>>(
        (const int4*)esrc, (const int4*)edst, (const float4*)ew, cnt, (uint4*)stage, nE4);
    scan_lookback<<<nb, 256, 0, s2>>>(cnt, rp, cursor, ctr, aggs, M, nb, nE);
    scatter_staged<<<(nE4 + 1 + 255) / 256, 256, 0, s2>>>(
        (const uint4*)stage, (const int4*)edst, cursor, pe, nE4, esrc, edst, ew, nE);
    cudaEventRecord(evJ, s2);

    conv_weights<<<160, 256>>>(W1, Wh, W1h, W1l, Whh, Whl);
    mma_gemm128<<<gemmBlocks, 256, SM_U32 * 4>>>(x, W1h, W1l, Ah, M, NFEAT);

    cudaStreamWaitEvent(0, evJ, 0);   // join

    // Layer 1 aggregation (fp16 out)
    spmm_csr128h<<<spmmBlocks, 256>>>(Ah, rp, pe, b1, Bh, M);

    // Layer 2 (fp16 native path)
    mma_gemm128_f16<<<gemmBlocks, 256, SM_U32 * 4>>>(Bh, Whh, Whl, Ah, M);
    spmm_csr128h<<<spmmBlocks, 256>>>(Ah, rp, pe, bh, Bh, M);

    // Layer 3 + log_softmax
    sgemm40<<<(M + 31) / 32, 256>>>(Bh, W2, Ch, M);
    spmm_csr40_lsm<<<spmmBlocks, 256>>>(Ch, rp, pe, b2, out, M);
}